// round 2
// baseline (speedup 1.0000x reference)
#include <cuda_runtime.h>
#include <cuda_bf16.h>
#include <math.h>

#define B_   4
#define L_   2048
#define DM_  512
#define H_   2
#define DK_  64
#define HD_  128   // H_*DK_

// ---------------- scratch (device globals; no allocation allowed) ----------
__device__ float g_q[B_ * L_ * HD_];
__device__ float g_k[B_ * L_ * HD_];
__device__ float g_v[B_ * L_ * HD_];
__device__ float g_o[B_ * L_ * HD_];
__device__ unsigned char g_mask[B_ * L_];

// ---------------- mask conversion (bool-u8 OR int32 -> u8) -----------------
__global__ void mask_convert_k(const unsigned char* __restrict__ p,
                               unsigned char* __restrict__ out, int n) {
    int tid = threadIdx.x;
    int any = 0;
    for (int i = tid; i < n; i += blockDim.x)
        if ((i & 3) != 0 && p[i] != 0) any = 1;
    any = __syncthreads_or(any);
    if (any) {
        // stored as 1-byte bool
        for (int i = tid; i < n; i += blockDim.x) out[i] = p[i] ? 1 : 0;
    } else {
        // stored as int32 (0/1)
        const int* pi = (const int*)p;
        for (int i = tid; i < n; i += blockDim.x) out[i] = pi[i] ? 1 : 0;
    }
}

// ---------------- generic SGEMM with bias: C[MxN] = A[MxK] @ W[KxN] + b ----
// BM=BN=128, BK=16, 256 threads, 8x8 per thread. M%128==0, N%128==0, K%16==0.
__global__ __launch_bounds__(256) void sgemm_bias_k(
    const float* __restrict__ A, const float* __restrict__ W,
    const float* __restrict__ bias, float* __restrict__ C,
    int M, int N, int K)
{
    __shared__ float As[16][128];
    __shared__ float Bs[16][128];
    const int tid = threadIdx.x;
    const int tx = tid & 15, ty = tid >> 4;
    const int bx = blockIdx.x, by = blockIdx.y;
    const float* Ab = A + (size_t)bx * 128 * K;
    const float* Wb = W + (size_t)by * 128;

    float acc[8][8];
#pragma unroll
    for (int i = 0; i < 8; i++)
#pragma unroll
        for (int j = 0; j < 8; j++) acc[i][j] = 0.f;

    for (int k0 = 0; k0 < K; k0 += 16) {
#pragma unroll
        for (int l = 0; l < 2; l++) {
            int idx = tid + l * 256;          // 0..511 float4s of A tile
            int row = idx >> 2;               // 0..127
            int c4  = idx & 3;                // 4 float4s per row (16 cols)
            float4 v = *(const float4*)(Ab + (size_t)row * K + k0 + c4 * 4);
            As[c4 * 4 + 0][row] = v.x;
            As[c4 * 4 + 1][row] = v.y;
            As[c4 * 4 + 2][row] = v.z;
            As[c4 * 4 + 3][row] = v.w;
        }
#pragma unroll
        for (int l = 0; l < 2; l++) {
            int idx = tid + l * 256;          // 0..511 float4s of W tile
            int row = idx >> 5;               // 16 rows
            int c4  = idx & 31;               // 32 float4s per row (128 cols)
            float4 v = *(const float4*)(Wb + (size_t)(k0 + row) * N + c4 * 4);
            *(float4*)&Bs[row][c4 * 4] = v;
        }
        __syncthreads();
#pragma unroll
        for (int kk = 0; kk < 16; kk++) {
            float ra[8], rb[8];
#pragma unroll
            for (int i = 0; i < 8; i++) ra[i] = As[kk][ty * 8 + i];
#pragma unroll
            for (int j = 0; j < 8; j++) rb[j] = Bs[kk][tx * 8 + j];
#pragma unroll
            for (int i = 0; i < 8; i++)
#pragma unroll
                for (int j = 0; j < 8; j++) acc[i][j] += ra[i] * rb[j];
        }
        __syncthreads();
    }
#pragma unroll
    for (int i = 0; i < 8; i++) {
        int row = bx * 128 + ty * 8 + i;
        float* Crow = C + (size_t)row * N + by * 128;
#pragma unroll
        for (int j = 0; j < 8; j++)
            Crow[tx * 8 + j] = acc[i][j] + bias[by * 128 + tx * 8 + j];
    }
}

// ---------------- scores: S = tanh(q·k^T/8)*10, masked -> attn buffer ------
// grid: (L/128, L/128, B*H); 256 thr; 8x8 per thread; K=64 in 2 chunks of 32
__global__ __launch_bounds__(256) void scores_k(
    const float* __restrict__ qp, const float* __restrict__ kp,
    const unsigned char* __restrict__ msk, float* __restrict__ attn)
{
    __shared__ float Qs[32][128];
    __shared__ float Ks[32][128];
    const int tid = threadIdx.x;
    const int tx = tid & 15, ty = tid >> 4;
    const int bh = blockIdx.z;
    const int b = bh / H_, h = bh % H_;
    const int q0 = blockIdx.x * 128, k0 = blockIdx.y * 128;
    const float* Qb = qp + ((size_t)b * L_ + q0) * HD_ + h * DK_;
    const float* Kb = kp + ((size_t)b * L_ + k0) * HD_ + h * DK_;

    float acc[8][8];
#pragma unroll
    for (int i = 0; i < 8; i++)
#pragma unroll
        for (int j = 0; j < 8; j++) acc[i][j] = 0.f;

    for (int d0 = 0; d0 < DK_; d0 += 32) {
#pragma unroll
        for (int l = 0; l < 4; l++) {
            int idx = tid + l * 256;          // 0..1023 float4s
            int row = idx >> 3;               // 128 rows
            int c4  = idx & 7;                // 8 float4s per row (32 cols)
            float4 v = *(const float4*)(Qb + (size_t)row * HD_ + d0 + c4 * 4);
            Qs[c4 * 4 + 0][row] = v.x;
            Qs[c4 * 4 + 1][row] = v.y;
            Qs[c4 * 4 + 2][row] = v.z;
            Qs[c4 * 4 + 3][row] = v.w;
            float4 w = *(const float4*)(Kb + (size_t)row * HD_ + d0 + c4 * 4);
            Ks[c4 * 4 + 0][row] = w.x;
            Ks[c4 * 4 + 1][row] = w.y;
            Ks[c4 * 4 + 2][row] = w.z;
            Ks[c4 * 4 + 3][row] = w.w;
        }
        __syncthreads();
#pragma unroll
        for (int kk = 0; kk < 32; kk++) {
            float ra[8], rb[8];
#pragma unroll
            for (int i = 0; i < 8; i++) ra[i] = Qs[kk][ty * 8 + i];
#pragma unroll
            for (int j = 0; j < 8; j++) rb[j] = Ks[kk][tx * 8 + j];
#pragma unroll
            for (int i = 0; i < 8; i++)
#pragma unroll
                for (int j = 0; j < 8; j++) acc[i][j] += ra[i] * rb[j];
        }
        __syncthreads();
    }
    const float inv = 0.125f;  // 1/sqrt(64)
#pragma unroll
    for (int i = 0; i < 8; i++) {
        size_t rowbase = (((size_t)bh) * L_ + (q0 + ty * 8 + i)) * L_;
#pragma unroll
        for (int j = 0; j < 8; j++) {
            int ki = k0 + tx * 8 + j;
            float s = tanhf(acc[i][j] * inv) * 10.0f;
            if (msk[b * L_ + ki]) s = -10.0f;
            attn[rowbase + ki] = s;
        }
    }
}

// ---------------- per-row log-softmax over Lk=2048 -------------------------
__global__ __launch_bounds__(256) void logsoftmax_k(float* __restrict__ attn) {
    __shared__ float red[256];
    const int tid = threadIdx.x;
    float* p = attn + (size_t)blockIdx.x * L_;
    float vals[8];
    float m = -1e30f;
#pragma unroll
    for (int l = 0; l < 2; l++) {
        float4 t = *(const float4*)(p + (tid + l * 256) * 4);
        vals[l * 4 + 0] = t.x; vals[l * 4 + 1] = t.y;
        vals[l * 4 + 2] = t.z; vals[l * 4 + 3] = t.w;
        m = fmaxf(m, fmaxf(fmaxf(t.x, t.y), fmaxf(t.z, t.w)));
    }
    red[tid] = m; __syncthreads();
    for (int s = 128; s > 0; s >>= 1) {
        if (tid < s) red[tid] = fmaxf(red[tid], red[tid + s]);
        __syncthreads();
    }
    float rm = red[0]; __syncthreads();
    float sum = 0.f;
#pragma unroll
    for (int e = 0; e < 8; e++) sum += expf(vals[e] - rm);
    red[tid] = sum; __syncthreads();
    for (int s = 128; s > 0; s >>= 1) {
        if (tid < s) red[tid] += red[tid + s];
        __syncthreads();
    }
    float lse = rm + logf(red[0]);
#pragma unroll
    for (int l = 0; l < 2; l++) {
        float4 t;
        t.x = vals[l * 4 + 0] - lse; t.y = vals[l * 4 + 1] - lse;
        t.z = vals[l * 4 + 2] - lse; t.w = vals[l * 4 + 3] - lse;
        *(float4*)(p + (tid + l * 256) * 4) = t;
    }
}

// ---------------- O = attn @ v  (per b,h) ----------------------------------
// grid: (L/128, B*H); block computes 128x64; 256 thr -> 8x4 per thread
__global__ __launch_bounds__(256) void av_k(
    const float* __restrict__ attn, const float* __restrict__ vp,
    float* __restrict__ op)
{
    __shared__ float As[32][128];   // [k][qi] transposed
    __shared__ float Vs[32][64];    // [k][d]
    const int tid = threadIdx.x;
    const int tx = tid & 15, ty = tid >> 4;
    const int bh = blockIdx.y;
    const int b = bh / H_, h = bh % H_;
    const int q0 = blockIdx.x * 128;
    const float* Ab = attn + ((size_t)bh * L_ + q0) * L_;
    const float* Vb = vp + (size_t)b * L_ * HD_ + h * DK_;

    float acc[8][4];
#pragma unroll
    for (int i = 0; i < 8; i++)
#pragma unroll
        for (int j = 0; j < 4; j++) acc[i][j] = 0.f;

    for (int k0 = 0; k0 < L_; k0 += 32) {
#pragma unroll
        for (int l = 0; l < 4; l++) {
            int idx = tid + l * 256;          // 1024 float4s of attn tile
            int row = idx >> 3;               // 128 rows (qi)
            int c4  = idx & 7;                // 8 float4s per row (32 k)
            float4 v = *(const float4*)(Ab + (size_t)row * L_ + k0 + c4 * 4);
            As[c4 * 4 + 0][row] = v.x;
            As[c4 * 4 + 1][row] = v.y;
            As[c4 * 4 + 2][row] = v.z;
            As[c4 * 4 + 3][row] = v.w;
        }
#pragma unroll
        for (int l = 0; l < 2; l++) {
            int idx = tid + l * 256;          // 512 float4s of V tile
            int row = idx >> 4;               // 32 rows (k)
            int c4  = idx & 15;               // 16 float4s per row (64 d)
            float4 v = *(const float4*)(Vb + (size_t)(k0 + row) * HD_ + c4 * 4);
            *(float4*)&Vs[row][c4 * 4] = v;
        }
        __syncthreads();
#pragma unroll
        for (int kk = 0; kk < 32; kk++) {
            float ra[8], rb[4];
#pragma unroll
            for (int i = 0; i < 8; i++) ra[i] = As[kk][ty * 8 + i];
#pragma unroll
            for (int j = 0; j < 4; j++) rb[j] = Vs[kk][tx * 4 + j];
#pragma unroll
            for (int i = 0; i < 8; i++)
#pragma unroll
                for (int j = 0; j < 4; j++) acc[i][j] += ra[i] * rb[j];
        }
        __syncthreads();
    }
#pragma unroll
    for (int i = 0; i < 8; i++) {
        float* Orow = op + ((size_t)b * L_ + q0 + ty * 8 + i) * HD_ + h * DK_;
#pragma unroll
        for (int j = 0; j < 4; j++) Orow[tx * 4 + j] = acc[i][j];
    }
}

// ---------------- launch ---------------------------------------------------
extern "C" void kernel_launch(void* const* d_in, const int* in_sizes, int n_in,
                              void* d_out, int out_size) {
    const float* Q  = (const float*)d_in[0];
    const float* K  = (const float*)d_in[1];
    const float* V  = (const float*)d_in[2];
    const unsigned char* mask = (const unsigned char*)d_in[3];
    const float* Wq = (const float*)d_in[4];
    const float* bq = (const float*)d_in[5];
    const float* Wk = (const float*)d_in[6];
    const float* bk = (const float*)d_in[7];
    const float* Wv = (const float*)d_in[8];
    const float* bv = (const float*)d_in[9];
    const float* Wo = (const float*)d_in[10];
    const float* bo = (const float*)d_in[11];

    float* out  = (float*)d_out;                       // (B, Lq, 512)
    float* attn = out + (size_t)B_ * L_ * DM_;         // (B, H, Lq, Lk)

    float *gq, *gk, *gv, *go;
    unsigned char* gm;
    cudaGetSymbolAddress((void**)&gq, g_q);
    cudaGetSymbolAddress((void**)&gk, g_k);
    cudaGetSymbolAddress((void**)&gv, g_v);
    cudaGetSymbolAddress((void**)&go, g_o);
    cudaGetSymbolAddress((void**)&gm, g_mask);

    mask_convert_k<<<1, 256>>>(mask, gm, B_ * L_);

    const int M = B_ * L_;  // 8192
    sgemm_bias_k<<<dim3(M / 128, 1), 256>>>(Q, Wq, bq, gq, M, HD_, DM_);
    sgemm_bias_k<<<dim3(M / 128, 1), 256>>>(K, Wk, bk, gk, M, HD_, DM_);
    sgemm_bias_k<<<dim3(M / 128, 1), 256>>>(V, Wv, bv, gv, M, HD_, DM_);

    scores_k<<<dim3(L_ / 128, L_ / 128, B_ * H_), 256>>>(gq, gk, gm, attn);
    logsoftmax_k<<<B_ * H_ * L_, 256>>>(attn);
    av_k<<<dim3(L_ / 128, B_ * H_), 256>>>(attn, gv, go);

    sgemm_bias_k<<<dim3(M / 128, DM_ / 128), 256>>>(go, Wo, bo, out, M, DM_, HD_);
}

// round 3
// speedup vs baseline: 1.3750x; 1.3750x over previous
#include <cuda_runtime.h>
#include <cuda_bf16.h>
#include <math.h>

#define B_   4
#define L_   2048
#define DM_  512
#define H_   2
#define DK_  64
#define HD_  128   // H_*DK_
#define BH_  (B_ * H_)

typedef unsigned long long ull;

// ---------------- scratch (device globals; no allocation allowed) ----------
__device__ float g_q[B_ * L_ * HD_];
__device__ float g_k[B_ * L_ * HD_];
__device__ float g_v[B_ * L_ * HD_];
__device__ float g_o[B_ * L_ * HD_];
__device__ float g_pmax[BH_ * L_ * 16];
__device__ float g_psum[BH_ * L_ * 16];
__device__ float g_lse[BH_ * L_];
__device__ unsigned char g_mask[B_ * L_];

// ---------------- packed f32x2 helpers -------------------------------------
__device__ __forceinline__ ull pack2(float x, float y) {
    ull r; asm("mov.b64 %0, {%1,%2};" : "=l"(r) : "f"(x), "f"(y)); return r;
}
__device__ __forceinline__ void unpack2(ull v, float& x, float& y) {
    asm("mov.b64 {%0,%1}, %2;" : "=f"(x), "=f"(y) : "l"(v));
}
__device__ __forceinline__ void ffma2(ull& d, ull a, ull b) {
    asm("fma.rn.f32x2 %0, %1, %2, %3;" : "=l"(d) : "l"(a), "l"(b), "l"(d));
}
__device__ __forceinline__ float tanh_fast(float x) {
    float r; asm("tanh.approx.f32 %0, %1;" : "=f"(r) : "f"(x)); return r;
}

// ---------------- mask conversion (bool-u8 OR int32 -> u8) -----------------
__global__ void mask_convert_k(const unsigned char* __restrict__ p,
                               unsigned char* __restrict__ out, int n) {
    int tid = threadIdx.x;
    int any = 0;
    for (int i = tid; i < n; i += blockDim.x)
        if ((i & 3) != 0 && p[i] != 0) any = 1;
    any = __syncthreads_or(any);
    if (any) {
        for (int i = tid; i < n; i += blockDim.x) out[i] = p[i] ? 1 : 0;
    } else {
        const int* pi = (const int*)p;
        for (int i = tid; i < n; i += blockDim.x) out[i] = pi[i] ? 1 : 0;
    }
}

// ---------------- SGEMM (3-way by blockIdx.z): C = A @ W + b ---------------
// BM=64, BN=128, BK=16, 256 threads, 4x8 per thread (packed f32x2 along N).
__global__ __launch_bounds__(256) void sgemm3_k(
    const float* __restrict__ A0, const float* __restrict__ A1, const float* __restrict__ A2,
    const float* __restrict__ W0, const float* __restrict__ W1, const float* __restrict__ W2,
    const float* __restrict__ b0, const float* __restrict__ b1, const float* __restrict__ b2,
    float* __restrict__ C0, float* __restrict__ C1, float* __restrict__ C2,
    int M, int N, int K)
{
    const float *A, *W, *bias; float* C;
    if (blockIdx.z == 0)      { A = A0; W = W0; bias = b0; C = C0; }
    else if (blockIdx.z == 1) { A = A1; W = W1; bias = b1; C = C1; }
    else                      { A = A2; W = W2; bias = b2; C = C2; }

    __shared__ float As[16][65];
    __shared__ float Bs[16][128];
    const int tid = threadIdx.x;
    const int tx = tid & 15, ty = tid >> 4;
    const float* Ab = A + (size_t)blockIdx.x * 64 * K;
    const float* Wb = W + (size_t)blockIdx.y * 128;

    ull acc[4][4];
#pragma unroll
    for (int i = 0; i < 4; i++)
#pragma unroll
        for (int j = 0; j < 4; j++) acc[i][j] = 0ull;

    for (int k0 = 0; k0 < K; k0 += 16) {
        {   // A tile: 64x16 = 256 float4, 1 per thread, transposed into As
            int row = tid >> 2, c4 = tid & 3;
            float4 v = *(const float4*)(Ab + (size_t)row * K + k0 + c4 * 4);
            As[c4 * 4 + 0][row] = v.x;
            As[c4 * 4 + 1][row] = v.y;
            As[c4 * 4 + 2][row] = v.z;
            As[c4 * 4 + 3][row] = v.w;
        }
#pragma unroll
        for (int l = 0; l < 2; l++) {   // B tile: 16x128 = 512 float4
            int idx = tid + l * 256;
            int row = idx >> 5, c4 = idx & 31;
            *(float4*)&Bs[row][c4 * 4] =
                *(const float4*)(Wb + (size_t)(k0 + row) * N + c4 * 4);
        }
        __syncthreads();
#pragma unroll
        for (int kk = 0; kk < 16; kk++) {
            ull a2[4];
#pragma unroll
            for (int i = 0; i < 4; i++) {
                float a = As[kk][ty * 4 + i];
                a2[i] = pack2(a, a);
            }
            ulonglong2 bb0 = *(const ulonglong2*)&Bs[kk][tx * 8];
            ulonglong2 bb1 = *(const ulonglong2*)&Bs[kk][tx * 8 + 4];
#pragma unroll
            for (int i = 0; i < 4; i++) {
                ffma2(acc[i][0], a2[i], bb0.x);
                ffma2(acc[i][1], a2[i], bb0.y);
                ffma2(acc[i][2], a2[i], bb1.x);
                ffma2(acc[i][3], a2[i], bb1.y);
            }
        }
        __syncthreads();
    }
    float4 ba = *(const float4*)(bias + blockIdx.y * 128 + tx * 8);
    float4 bbv = *(const float4*)(bias + blockIdx.y * 128 + tx * 8 + 4);
#pragma unroll
    for (int i = 0; i < 4; i++) {
        int row = blockIdx.x * 64 + ty * 4 + i;
        float* Crow = C + (size_t)row * N + blockIdx.y * 128 + tx * 8;
        float4 o0, o1;
        unpack2(acc[i][0], o0.x, o0.y);
        unpack2(acc[i][1], o0.z, o0.w);
        unpack2(acc[i][2], o1.x, o1.y);
        unpack2(acc[i][3], o1.z, o1.w);
        o0.x += ba.x;  o0.y += ba.y;  o0.z += ba.z;  o0.w += ba.w;
        o1.x += bbv.x; o1.y += bbv.y; o1.z += bbv.z; o1.w += bbv.w;
        *(float4*)Crow = o0;
        *(float4*)(Crow + 4) = o1;
    }
}

// ---------------- scores: S = masked tanh(q.k/8)*10 + row partial stats ----
// grid (Lq/128, Lk/128, B*H), 256 thr, 8x8 per thread, K=64 in 2 chunks.
__global__ __launch_bounds__(256) void scores_k(
    const float* __restrict__ qp, const float* __restrict__ kp,
    const unsigned char* __restrict__ msk, float* __restrict__ attn,
    float* __restrict__ pmax, float* __restrict__ psum)
{
    __shared__ float Qs[32][132];
    __shared__ float Ks[32][132];
    const int tid = threadIdx.x;
    const int tx = tid & 15, ty = tid >> 4;
    const int bh = blockIdx.z;
    const int b = bh / H_;
    const int q0 = blockIdx.x * 128, k0 = blockIdx.y * 128;
    const float* Qb = qp + ((size_t)b * L_ + q0) * HD_ + (bh % H_) * DK_;
    const float* Kb = kp + ((size_t)b * L_ + k0) * HD_ + (bh % H_) * DK_;

    ull acc[8][4];
#pragma unroll
    for (int i = 0; i < 8; i++)
#pragma unroll
        for (int j = 0; j < 4; j++) acc[i][j] = 0ull;

    for (int d0 = 0; d0 < DK_; d0 += 32) {
#pragma unroll
        for (int l = 0; l < 4; l++) {   // each tile: 128x32 = 1024 float4
            int idx = tid + l * 256;
            int row = idx >> 3, c4 = idx & 7;
            float4 v = *(const float4*)(Qb + (size_t)row * HD_ + d0 + c4 * 4);
            Qs[c4 * 4 + 0][row] = v.x;
            Qs[c4 * 4 + 1][row] = v.y;
            Qs[c4 * 4 + 2][row] = v.z;
            Qs[c4 * 4 + 3][row] = v.w;
            float4 w = *(const float4*)(Kb + (size_t)row * HD_ + d0 + c4 * 4);
            Ks[c4 * 4 + 0][row] = w.x;
            Ks[c4 * 4 + 1][row] = w.y;
            Ks[c4 * 4 + 2][row] = w.z;
            Ks[c4 * 4 + 3][row] = w.w;
        }
        __syncthreads();
#pragma unroll
        for (int kk = 0; kk < 32; kk++) {
            float4 qa = *(const float4*)&Qs[kk][ty * 8];
            float4 qb = *(const float4*)&Qs[kk][ty * 8 + 4];
            ulonglong2 kb0 = *(const ulonglong2*)&Ks[kk][tx * 8];
            ulonglong2 kb1 = *(const ulonglong2*)&Ks[kk][tx * 8 + 4];
            ull a2[8];
            a2[0] = pack2(qa.x, qa.x); a2[1] = pack2(qa.y, qa.y);
            a2[2] = pack2(qa.z, qa.z); a2[3] = pack2(qa.w, qa.w);
            a2[4] = pack2(qb.x, qb.x); a2[5] = pack2(qb.y, qb.y);
            a2[6] = pack2(qb.z, qb.z); a2[7] = pack2(qb.w, qb.w);
#pragma unroll
            for (int i = 0; i < 8; i++) {
                ffma2(acc[i][0], a2[i], kb0.x);
                ffma2(acc[i][1], a2[i], kb0.y);
                ffma2(acc[i][2], a2[i], kb1.x);
                ffma2(acc[i][3], a2[i], kb1.y);
            }
        }
        __syncthreads();
    }

    // epilogue: tanh clip + mask, write raw S, reduce per-row max & sumexp
    bool m[8];
#pragma unroll
    for (int j = 0; j < 8; j++) m[j] = msk[b * L_ + k0 + tx * 8 + j] != 0;

    const int kt = blockIdx.y;
#pragma unroll
    for (int i = 0; i < 8; i++) {
        int row = q0 + ty * 8 + i;
        float sv[8];
        unpack2(acc[i][0], sv[0], sv[1]);
        unpack2(acc[i][1], sv[2], sv[3]);
        unpack2(acc[i][2], sv[4], sv[5]);
        unpack2(acc[i][3], sv[6], sv[7]);
        float rmax = -1e30f;
#pragma unroll
        for (int j = 0; j < 8; j++) {
            float s = tanh_fast(sv[j] * 0.125f) * 10.0f;
            if (m[j]) s = -10.0f;
            sv[j] = s;
            rmax = fmaxf(rmax, s);
        }
#pragma unroll
        for (int off = 8; off > 0; off >>= 1)
            rmax = fmaxf(rmax, __shfl_xor_sync(0xffffffffu, rmax, off));
        float sum = 0.f;
#pragma unroll
        for (int j = 0; j < 8; j++) sum += __expf(sv[j] - rmax);
#pragma unroll
        for (int off = 8; off > 0; off >>= 1)
            sum += __shfl_xor_sync(0xffffffffu, sum, off);

        float* dst = attn + ((size_t)bh * L_ + row) * L_ + k0 + tx * 8;
        *(float4*)dst       = make_float4(sv[0], sv[1], sv[2], sv[3]);
        *(float4*)(dst + 4) = make_float4(sv[4], sv[5], sv[6], sv[7]);
        if (tx == 0) {
            size_t pidx = (((size_t)bh * L_ + row) << 4) + kt;
            pmax[pidx] = rmax;
            psum[pidx] = sum;
        }
    }
}

// ---------------- lse finalize: merge 16 partials per row ------------------
__global__ __launch_bounds__(256) void lse_k(
    const float* __restrict__ pmax, const float* __restrict__ psum,
    float* __restrict__ lse)
{
    int i = blockIdx.x * 256 + threadIdx.x;
    if (i >= BH_ * L_) return;
    const float* pm = pmax + ((size_t)i << 4);
    const float* ps = psum + ((size_t)i << 4);
    float gm = -1e30f;
#pragma unroll
    for (int t = 0; t < 16; t++) gm = fmaxf(gm, pm[t]);
    float s = 0.f;
#pragma unroll
    for (int t = 0; t < 16; t++) s += ps[t] * __expf(pm[t] - gm);
    lse[i] = gm + logf(s);
}

// ---------------- fused attn-write + AV: out = (S-lse) @ V -----------------
// grid (Lq/64, B*H), 256 thr, 64x64 tile, 4x4 per thread (packed along d).
__global__ __launch_bounds__(256) void av_k(
    float* __restrict__ attn, const float* __restrict__ vp,
    const float* __restrict__ lse, float* __restrict__ op)
{
    __shared__ float As[32][65];
    __shared__ float Vs[32][68];
    __shared__ float lse_s[64];
    const int tid = threadIdx.x;
    const int tx = tid & 15, ty = tid >> 4;
    const int bh = blockIdx.y;
    const int b = bh / H_;
    const int q0 = blockIdx.x * 64;
    float* Ab = attn + ((size_t)bh * L_ + q0) * L_;
    const float* Vb = vp + (size_t)b * L_ * HD_ + (bh % H_) * DK_;

    if (tid < 64) lse_s[tid] = lse[bh * L_ + q0 + tid];
    __syncthreads();

    ull acc[4][2];
#pragma unroll
    for (int i = 0; i < 4; i++) { acc[i][0] = 0ull; acc[i][1] = 0ull; }

    for (int k0 = 0; k0 < L_; k0 += 32) {
#pragma unroll
        for (int l = 0; l < 2; l++) {   // S tile: 64x32 = 512 float4
            int idx = tid + l * 256;
            int row = idx >> 3, c4 = idx & 7;
            float* p = Ab + (size_t)row * L_ + k0 + c4 * 4;
            float4 v = *(const float4*)p;
            float ls = lse_s[row];
            v.x -= ls; v.y -= ls; v.z -= ls; v.w -= ls;
            *(float4*)p = v;                 // finalize attn in place
            As[c4 * 4 + 0][row] = v.x;
            As[c4 * 4 + 1][row] = v.y;
            As[c4 * 4 + 2][row] = v.z;
            As[c4 * 4 + 3][row] = v.w;
        }
#pragma unroll
        for (int l = 0; l < 2; l++) {   // V tile: 32x64 = 512 float4
            int idx = tid + l * 256;
            int row = idx >> 4, c4 = idx & 15;
            *(float4*)&Vs[row][c4 * 4] =
                *(const float4*)(Vb + (size_t)(k0 + row) * HD_ + c4 * 4);
        }
        __syncthreads();
#pragma unroll
        for (int kk = 0; kk < 32; kk++) {
            ull a2[4];
#pragma unroll
            for (int i = 0; i < 4; i++) {
                float a = As[kk][ty * 4 + i];
                a2[i] = pack2(a, a);
            }
            ulonglong2 bb = *(const ulonglong2*)&Vs[kk][tx * 4];
#pragma unroll
            for (int i = 0; i < 4; i++) {
                ffma2(acc[i][0], a2[i], bb.x);
                ffma2(acc[i][1], a2[i], bb.y);
            }
        }
        __syncthreads();
    }
#pragma unroll
    for (int i = 0; i < 4; i++) {
        float4 o;
        unpack2(acc[i][0], o.x, o.y);
        unpack2(acc[i][1], o.z, o.w);
        float* Orow = op + ((size_t)b * L_ + q0 + ty * 4 + i) * HD_
                      + (bh % H_) * DK_ + tx * 4;
        *(float4*)Orow = o;
    }
}

// ---------------- launch ---------------------------------------------------
extern "C" void kernel_launch(void* const* d_in, const int* in_sizes, int n_in,
                              void* d_out, int out_size) {
    const float* Q  = (const float*)d_in[0];
    const float* K  = (const float*)d_in[1];
    const float* V  = (const float*)d_in[2];
    const unsigned char* mask = (const unsigned char*)d_in[3];
    const float* Wq = (const float*)d_in[4];
    const float* bq = (const float*)d_in[5];
    const float* Wk = (const float*)d_in[6];
    const float* bk = (const float*)d_in[7];
    const float* Wv = (const float*)d_in[8];
    const float* bv = (const float*)d_in[9];
    const float* Wo = (const float*)d_in[10];
    const float* bo = (const float*)d_in[11];

    float* out  = (float*)d_out;                       // (B, Lq, 512)
    float* attn = out + (size_t)B_ * L_ * DM_;         // (B, H, Lq, Lk)

    float *gq, *gk, *gv, *go, *gpm, *gps, *gl;
    unsigned char* gm;
    cudaGetSymbolAddress((void**)&gq, g_q);
    cudaGetSymbolAddress((void**)&gk, g_k);
    cudaGetSymbolAddress((void**)&gv, g_v);
    cudaGetSymbolAddress((void**)&go, g_o);
    cudaGetSymbolAddress((void**)&gpm, g_pmax);
    cudaGetSymbolAddress((void**)&gps, g_psum);
    cudaGetSymbolAddress((void**)&gl, g_lse);
    cudaGetSymbolAddress((void**)&gm, g_mask);

    mask_convert_k<<<1, 256>>>(mask, gm, B_ * L_);

    const int M = B_ * L_;  // 8192
    // fused QKV projections: z selects (Q,Wq)->(gq), (K,Wk)->(gk), (V,Wv)->(gv)
    sgemm3_k<<<dim3(M / 64, 1, 3), 256>>>(Q, K, V, Wq, Wk, Wv, bq, bk, bv,
                                          gq, gk, gv, M, HD_, DM_);

    scores_k<<<dim3(L_ / 128, L_ / 128, BH_), 256>>>(gq, gk, gm, attn, gpm, gps);
    lse_k<<<(BH_ * L_ + 255) / 256, 256>>>(gpm, gps, gl);
    av_k<<<dim3(L_ / 64, BH_), 256>>>(attn, gv, gl, go);

    // output projection
    sgemm3_k<<<dim3(M / 64, DM_ / 128, 1), 256>>>(go, go, go, Wo, Wo, Wo,
                                                  bo, bo, bo, out, out, out,
                                                  M, DM_, HD_);
}

// round 13
// speedup vs baseline: 1.6603x; 1.2075x over previous
#include <cuda_runtime.h>
#include <cuda_bf16.h>
#include <math.h>
#include <stdint.h>

#define B_   4
#define L_   2048
#define DM_  512
#define H_   2
#define DK_  64
#define HD_  128   // H_*DK_
#define BH_  (B_ * H_)

typedef unsigned long long ull;

// ---------------- scratch (device globals; no allocation allowed) ----------
__device__ __align__(16) float g_q[B_ * L_ * HD_];
__device__ __align__(16) float g_k[B_ * L_ * HD_];
__device__ __align__(16) float g_v[B_ * L_ * HD_];
__device__ __align__(16) float g_o[B_ * L_ * HD_];
__device__ __align__(16) float g_pmax[BH_ * L_ * 32];
__device__ __align__(16) float g_psum[BH_ * L_ * 32];
__device__ __align__(16) float g_lse[BH_ * L_];
__device__ __align__(16) __nv_bfloat16 g_vthi[BH_ * DK_ * L_];  // V^T hi: [bh][d][k]
__device__ __align__(16) __nv_bfloat16 g_vtlo[BH_ * DK_ * L_];  // V^T lo
__device__ unsigned char g_mask[B_ * L_];

// ---------------- small helpers --------------------------------------------
__device__ __forceinline__ ull pack2(float x, float y) {
    ull r; asm("mov.b64 %0, {%1,%2};" : "=l"(r) : "f"(x), "f"(y)); return r;
}
__device__ __forceinline__ void unpack2(ull v, float& x, float& y) {
    asm("mov.b64 {%0,%1}, %2;" : "=f"(x), "=f"(y) : "l"(v));
}
__device__ __forceinline__ void ffma2(ull& d, ull a, ull b) {
    asm("fma.rn.f32x2 %0, %1, %2, %3;" : "=l"(d) : "l"(a), "l"(b), "l"(d));
}
__device__ __forceinline__ float tanh_fast(float x) {
    float r; asm("tanh.approx.f32 %0, %1;" : "=f"(r) : "f"(x)); return r;
}
// split (a,b) fp32 -> packed bf16x2 hi (rounded) and lo (residual rounded)
__device__ __forceinline__ void split2(float a, float b, uint32_t& hi, uint32_t& lo) {
    asm("cvt.rn.bf16x2.f32 %0, %1, %2;" : "=r"(hi) : "f"(b), "f"(a));
    float ha = __uint_as_float(hi << 16);
    float hb = __uint_as_float(hi & 0xffff0000u);
    float ra = a - ha, rb = b - hb;
    asm("cvt.rn.bf16x2.f32 %0, %1, %2;" : "=r"(lo) : "f"(rb), "f"(ra));
}
__device__ __forceinline__ uint32_t smem_u32(const void* p) {
    uint32_t a;
    asm("{ .reg .u64 t; cvta.to.shared.u64 t, %1; cvt.u32.u64 %0, t; }"
        : "=r"(a) : "l"(p));
    return a;
}
__device__ __forceinline__ void ldsm4(uint32_t& d0, uint32_t& d1,
                                     uint32_t& d2, uint32_t& d3, uint32_t addr) {
    asm volatile("ldmatrix.sync.aligned.m8n8.x4.shared.b16 {%0,%1,%2,%3}, [%4];"
        : "=r"(d0), "=r"(d1), "=r"(d2), "=r"(d3) : "r"(addr));
}
__device__ __forceinline__ void mma16816(float* c, const uint32_t* a,
                                         uint32_t b0, uint32_t b1) {
    asm volatile(
        "mma.sync.aligned.m16n8k16.row.col.f32.bf16.bf16.f32 "
        "{%0,%1,%2,%3}, {%4,%5,%6,%7}, {%8,%9}, {%0,%1,%2,%3};"
        : "+f"(c[0]), "+f"(c[1]), "+f"(c[2]), "+f"(c[3])
        : "r"(a[0]), "r"(a[1]), "r"(a[2]), "r"(a[3]), "r"(b0), "r"(b1));
}

// ---------------- mask conversion (bool-u8 OR int32 -> u8) -----------------
__global__ void mask_convert_k(const unsigned char* __restrict__ p,
                               unsigned char* __restrict__ out, int n) {
    int tid = threadIdx.x;
    int any = 0;
    for (int i = tid; i < n; i += blockDim.x)
        if ((i & 3) != 0 && p[i] != 0) any = 1;
    any = __syncthreads_or(any);
    if (any) {
        for (int i = tid; i < n; i += blockDim.x) out[i] = p[i] ? 1 : 0;
    } else {
        const int* pi = (const int*)p;
        for (int i = tid; i < n; i += blockDim.x) out[i] = pi[i] ? 1 : 0;
    }
}

// ---------------- SGEMM (3-way by blockIdx.z): C = A @ W + b (fp32/FFMA2) --
__global__ __launch_bounds__(256) void sgemm3_k(
    const float* __restrict__ A0, const float* __restrict__ A1, const float* __restrict__ A2,
    const float* __restrict__ W0, const float* __restrict__ W1, const float* __restrict__ W2,
    const float* __restrict__ b0, const float* __restrict__ b1, const float* __restrict__ b2,
    float* __restrict__ C0, float* __restrict__ C1, float* __restrict__ C2,
    int M, int N, int K)
{
    const float *A, *W, *bias; float* C;
    if (blockIdx.z == 0)      { A = A0; W = W0; bias = b0; C = C0; }
    else if (blockIdx.z == 1) { A = A1; W = W1; bias = b1; C = C1; }
    else                      { A = A2; W = W2; bias = b2; C = C2; }

    __shared__ float As[16][65];
    __shared__ float Bs[16][128];
    const int tid = threadIdx.x;
    const int tx = tid & 15, ty = tid >> 4;
    const float* Ab = A + (size_t)blockIdx.x * 64 * K;
    const float* Wb = W + (size_t)blockIdx.y * 128;

    ull acc[4][4];
#pragma unroll
    for (int i = 0; i < 4; i++)
#pragma unroll
        for (int j = 0; j < 4; j++) acc[i][j] = 0ull;

    for (int k0 = 0; k0 < K; k0 += 16) {
        {
            int row = tid >> 2, c4 = tid & 3;
            float4 v = *(const float4*)(Ab + (size_t)row * K + k0 + c4 * 4);
            As[c4 * 4 + 0][row] = v.x;
            As[c4 * 4 + 1][row] = v.y;
            As[c4 * 4 + 2][row] = v.z;
            As[c4 * 4 + 3][row] = v.w;
        }
#pragma unroll
        for (int l = 0; l < 2; l++) {
            int idx = tid + l * 256;
            int row = idx >> 5, c4 = idx & 31;
            *(float4*)&Bs[row][c4 * 4] =
                *(const float4*)(Wb + (size_t)(k0 + row) * N + c4 * 4);
        }
        __syncthreads();
#pragma unroll
        for (int kk = 0; kk < 16; kk++) {
            ull a2[4];
#pragma unroll
            for (int i = 0; i < 4; i++) {
                float a = As[kk][ty * 4 + i];
                a2[i] = pack2(a, a);
            }
            ulonglong2 bb0 = *(const ulonglong2*)&Bs[kk][tx * 8];
            ulonglong2 bb1 = *(const ulonglong2*)&Bs[kk][tx * 8 + 4];
#pragma unroll
            for (int i = 0; i < 4; i++) {
                ffma2(acc[i][0], a2[i], bb0.x);
                ffma2(acc[i][1], a2[i], bb0.y);
                ffma2(acc[i][2], a2[i], bb1.x);
                ffma2(acc[i][3], a2[i], bb1.y);
            }
        }
        __syncthreads();
    }
    float4 ba = *(const float4*)(bias + blockIdx.y * 128 + tx * 8);
    float4 bbv = *(const float4*)(bias + blockIdx.y * 128 + tx * 8 + 4);
#pragma unroll
    for (int i = 0; i < 4; i++) {
        int row = blockIdx.x * 64 + ty * 4 + i;
        float* Crow = C + (size_t)row * N + blockIdx.y * 128 + tx * 8;
        float4 o0, o1;
        unpack2(acc[i][0], o0.x, o0.y);
        unpack2(acc[i][1], o0.z, o0.w);
        unpack2(acc[i][2], o1.x, o1.y);
        unpack2(acc[i][3], o1.z, o1.w);
        o0.x += ba.x;  o0.y += ba.y;  o0.z += ba.z;  o0.w += ba.w;
        o1.x += bbv.x; o1.y += bbv.y; o1.z += bbv.z; o1.w += bbv.w;
        *(float4*)Crow = o0;
        *(float4*)(Crow + 4) = o1;
    }
}

// ---------------- V transpose + bf16 split:  VT[bh][d][k] ------------------
__global__ __launch_bounds__(256) void vsplit_k(
    const float* __restrict__ vp,
    __nv_bfloat16* __restrict__ vthi, __nv_bfloat16* __restrict__ vtlo)
{
    __shared__ float t[128][68];   // stride 272B = 17*16 (float4-aligned rows)
    const int tid = threadIdx.x;
    const int bh = blockIdx.y, b = bh >> 1, h = bh & 1;
    const int k0 = blockIdx.x * 128;
    const float* Vb = vp + ((size_t)b * L_ + k0) * HD_ + h * DK_;
#pragma unroll
    for (int l = 0; l < 8; l++) {
        int idx = tid + l * 256;
        int row = idx >> 4, c4 = idx & 15;
        float4 v = *(const float4*)(Vb + (size_t)row * HD_ + c4 * 4);
        *(float4*)&t[row][c4 * 4] = v;
    }
    __syncthreads();
#pragma unroll
    for (int l = 0; l < 4; l++) {
        int task = tid + l * 256;          // 0..1023
        int d = task >> 4, kc = task & 15; // 8 k's per task
        float x[8];
#pragma unroll
        for (int i = 0; i < 8; i++) x[i] = t[kc * 8 + i][d];
        uint32_t hi[4], lo[4];
#pragma unroll
        for (int i = 0; i < 4; i++) split2(x[2 * i], x[2 * i + 1], hi[i], lo[i]);
        size_t off = ((size_t)bh * DK_ + d) * L_ + k0 + kc * 8;
        *(uint4*)(vthi + off) = make_uint4(hi[0], hi[1], hi[2], hi[3]);
        *(uint4*)(vtlo + off) = make_uint4(lo[0], lo[1], lo[2], lo[3]);
    }
}

// ---------------- scores via mma.sync bf16 split ---------------------------
// grid (Lq/128, Lk/128, B*H), 256 thr (8 warps, 4x2 of 32x64 tiles).
// SMEM: mask 128B; Qhi/Qlo/Khi/Klo [128][72] bf16 (stride 144B).
#define SC_QH 128
#define SC_QL (SC_QH + 18432)
#define SC_KH (SC_QH + 2 * 18432)
#define SC_KL (SC_QH + 3 * 18432)
#define SC_SMEM (SC_QH + 4 * 18432)
__global__ __launch_bounds__(256) void scores_mma_k(
    const float* __restrict__ qp, const float* __restrict__ kp,
    const unsigned char* __restrict__ msk, float* __restrict__ attn,
    float* __restrict__ pmax, float* __restrict__ psum)
{
    extern __shared__ char smem[];
    const uint32_t sbase = smem_u32(smem);
    const int tid = threadIdx.x, w = tid >> 5, lid = tid & 31;
    const int bh = blockIdx.z, b = bh >> 1, h = bh & 1;
    const int q0 = blockIdx.x * 128, k0 = blockIdx.y * 128;
    const int wr = (w >> 1) * 32, wc = (w & 1) * 64;

    if (tid < 128) smem[tid] = (char)msk[b * L_ + k0 + tid];

    const float* Qb = qp + ((size_t)b * L_ + q0) * HD_ + h * DK_;
    const float* Kb = kp + ((size_t)b * L_ + k0) * HD_ + h * DK_;
#pragma unroll
    for (int l = 0; l < 8; l++) {          // Q: 128x64 fp32 = 2048 f4
        int idx = tid + l * 256;
        int row = idx >> 4, c4 = idx & 15;
        uint32_t off = (uint32_t)(row * 144 + c4 * 8);
        float4 v = *(const float4*)(Qb + (size_t)row * HD_ + c4 * 4);
        uint32_t h0, l0, h1, l1;
        split2(v.x, v.y, h0, l0); split2(v.z, v.w, h1, l1);
        *(uint2*)(smem + SC_QH + off) = make_uint2(h0, h1);
        *(uint2*)(smem + SC_QL + off) = make_uint2(l0, l1);
        float4 u = *(const float4*)(Kb + (size_t)row * HD_ + c4 * 4);
        split2(u.x, u.y, h0, l0); split2(u.z, u.w, h1, l1);
        *(uint2*)(smem + SC_KH + off) = make_uint2(h0, h1);
        *(uint2*)(smem + SC_KL + off) = make_uint2(l0, l1);
    }
    __syncthreads();

    float acc[2][8][4];
#pragma unroll
    for (int i = 0; i < 2; i++)
#pragma unroll
        for (int j = 0; j < 8; j++)
#pragma unroll
            for (int r = 0; r < 4; r++) acc[i][j][r] = 0.f;

    const uint32_t At[3] = {SC_QH, SC_QH, SC_QL};
    const uint32_t Bt[3] = {SC_KH, SC_KL, SC_KH};
#pragma unroll
    for (int p = 0; p < 3; p++) {
        const uint32_t ab = sbase + At[p], bb = sbase + Bt[p];
#pragma unroll
        for (int kf = 0; kf < 4; kf++) {
            uint32_t a[2][4];
#pragma unroll
            for (int mf = 0; mf < 2; mf++) {
                uint32_t addr = ab + (uint32_t)((wr + mf * 16 + (lid & 15)) * 144
                              + kf * 32 + (lid >> 4) * 16);
                ldsm4(a[mf][0], a[mf][1], a[mf][2], a[mf][3], addr);
            }
#pragma unroll
            for (int np = 0; np < 4; np++) {
                uint32_t d0, d1, d2, d3;
                uint32_t addr = bb + (uint32_t)((wc + np * 16 + ((lid >> 4) * 8)
                              + (lid & 7)) * 144 + kf * 32 + ((lid >> 3) & 1) * 16);
                ldsm4(d0, d1, d2, d3, addr);
#pragma unroll
                for (int mf = 0; mf < 2; mf++) {
                    mma16816(acc[mf][2 * np],     a[mf], d0, d1);
                    mma16816(acc[mf][2 * np + 1], a[mf], d2, d3);
                }
            }
        }
    }
    __syncthreads();   // all ldmatrix done; smem tiles reusable as staging

    float* stage = (float*)(smem + SC_QH);   // [128][132] fp32
    const int g = lid >> 2, qd = lid & 3;
#pragma unroll
    for (int mf = 0; mf < 2; mf++) {
#pragma unroll
        for (int rh = 0; rh < 2; rh++) {
            const int r = wr + mf * 16 + g + rh * 8;
            float vbuf[16];
            float m = -1e30f;
#pragma unroll
            for (int nf = 0; nf < 8; nf++) {
                int col = wc + nf * 8 + qd * 2;
                float t0 = tanh_fast(acc[mf][nf][rh * 2] * 0.125f) * 10.0f;
                float t1 = tanh_fast(acc[mf][nf][rh * 2 + 1] * 0.125f) * 10.0f;
                if (smem[col])     t0 = -10.0f;
                if (smem[col + 1]) t1 = -10.0f;
                vbuf[nf * 2] = t0; vbuf[nf * 2 + 1] = t1;
                m = fmaxf(m, fmaxf(t0, t1));
                *(float2*)(stage + r * 132 + col) = make_float2(t0, t1);
            }
            float s = 0.f;
#pragma unroll
            for (int e = 0; e < 16; e++) s += __expf(vbuf[e] - m);
#pragma unroll
            for (int off = 1; off <= 2; off <<= 1) {
                float mo = __shfl_xor_sync(0xffffffffu, m, off);
                float so = __shfl_xor_sync(0xffffffffu, s, off);
                float nm = fmaxf(m, mo);
                s = s * __expf(m - nm) + so * __expf(mo - nm);
                m = nm;
            }
            if (qd == 0) {
                size_t pidx = (((size_t)bh * L_ + q0 + r) << 5)
                            + blockIdx.y * 2 + (w & 1);
                pmax[pidx] = m;
                psum[pidx] = s;
            }
        }
    }
    __syncthreads();

    // coalesced copy staging -> attn
    float* dstb = attn + (((size_t)bh * L_ + q0)) * L_ + k0;
#pragma unroll
    for (int l = 0; l < 16; l++) {
        int idx = tid + l * 256;           // 4096 float4
        int row = idx >> 5, c4 = idx & 31;
        *(float4*)(dstb + (size_t)row * L_ + c4 * 4) =
            *(const float4*)(stage + row * 132 + c4 * 4);
    }
}

// ---------------- lse finalize: merge 32 partials per row ------------------
__global__ __launch_bounds__(256) void lse_k(
    const float* __restrict__ pmax, const float* __restrict__ psum,
    float* __restrict__ lse)
{
    int i = blockIdx.x * 256 + threadIdx.x;
    if (i >= BH_ * L_) return;
    const float* pm = pmax + ((size_t)i << 5);
    const float* ps = psum + ((size_t)i << 5);
    float gm = -1e30f;
#pragma unroll
    for (int t = 0; t < 32; t++) gm = fmaxf(gm, pm[t]);
    float s = 0.f;
#pragma unroll
    for (int t = 0; t < 32; t++) s += ps[t] * __expf(pm[t] - gm);
    lse[i] = gm + logf(s);
}

// ---------------- AV via mma.sync: finalize attn in place, O = attn @ V ----
// grid (Lq/64, B*H), 256 thr (8 warps, 4x2 of 16x32 tiles). K chunks of 64.
#define AV_AH 256
#define AV_AL (AV_AH + 9216)
#define AV_BH2 (AV_AH + 2 * 9216)
#define AV_BL2 (AV_AH + 3 * 9216)
#define AV_SMEM (AV_AH + 4 * 9216)
__global__ __launch_bounds__(256) void av_mma_k(
    float* __restrict__ attn, const __nv_bfloat16* __restrict__ vthi,
    const __nv_bfloat16* __restrict__ vtlo, const float* __restrict__ lse,
    float* __restrict__ op)
{
    __shared__ __align__(16) char smem[AV_SMEM];
    const uint32_t sbase = smem_u32(smem);
    const int tid = threadIdx.x, w = tid >> 5, lid = tid & 31;
    const int bh = blockIdx.y, b = bh >> 1, h = bh & 1;
    const int q0 = blockIdx.x * 64;
    const int wr = (w >> 1) * 16, wc = (w & 1) * 32;
    float* lse_s = (float*)smem;          // 64 floats

    if (tid < 64) lse_s[tid] = lse[bh * L_ + q0 + tid];

    float* Ag = attn + ((size_t)bh * L_ + q0) * L_;
    const __nv_bfloat16* Bhg = vthi + (size_t)bh * DK_ * L_;
    const __nv_bfloat16* Blg = vtlo + (size_t)bh * DK_ * L_;

    float acc[4][4];
#pragma unroll
    for (int i = 0; i < 4; i++)
#pragma unroll
        for (int j = 0; j < 4; j++) acc[i][j] = 0.f;

    const uint32_t At[3] = {AV_AH, AV_AH, AV_AL};
    const uint32_t Bt[3] = {AV_BH2, AV_BL2, AV_BH2};

    for (int c = 0; c < 32; c++) {
        const int k0 = c * 64;
        __syncthreads();                   // protect smem from prev iter reads
#pragma unroll
        for (int l = 0; l < 4; l++) {      // attn 64x64 fp32 = 1024 f4
            int idx = tid + l * 256;
            int row = idx >> 4, c4 = idx & 15;
            float* p = Ag + (size_t)row * L_ + k0 + c4 * 4;
            float4 v = *(const float4*)p;
            float ls = lse_s[row];
            v.x -= ls; v.y -= ls; v.z -= ls; v.w -= ls;
            *(float4*)p = v;               // finalized attn output
            uint32_t h0, l0, h1, l1;
            split2(v.x, v.y, h0, l0); split2(v.z, v.w, h1, l1);
            uint32_t off = (uint32_t)(row * 144 + c4 * 8);
            *(uint2*)(smem + AV_AH + off) = make_uint2(h0, h1);
            *(uint2*)(smem + AV_AL + off) = make_uint2(l0, l1);
        }
#pragma unroll
        for (int l = 0; l < 4; l++) {      // VT hi/lo: 2 x 64x64 bf16
            int idx = tid + l * 256;       // 1024 uint4s total
            int t = idx >> 9, row = (idx >> 3) & 63, ch = idx & 7;
            const __nv_bfloat16* src =
                (t ? Blg : Bhg) + (size_t)row * L_ + k0 + ch * 8;
            uint4 d = *(const uint4*)src;
            *(uint4*)(smem + (t ? AV_BL2 : AV_BH2) + row * 144 + ch * 16) = d;
        }
        __syncthreads();
#pragma unroll
        for (int p = 0; p < 3; p++) {
            const uint32_t ab = sbase + At[p], bb = sbase + Bt[p];
#pragma unroll
            for (int kf = 0; kf < 4; kf++) {
                uint32_t a[4];
                uint32_t addr = ab + (uint32_t)((wr + (lid & 15)) * 144
                              + kf * 32 + (lid >> 4) * 16);
                ldsm4(a[0], a[1], a[2], a[3], addr);
#pragma unroll
                for (int np = 0; np < 2; np++) {
                    uint32_t d0, d1, d2, d3;
                    uint32_t baddr = bb + (uint32_t)((wc + np * 16
                                   + ((lid >> 4) * 8) + (lid & 7)) * 144
                                   + kf * 32 + ((lid >> 3) & 1) * 16);
                    ldsm4(d0, d1, d2, d3, baddr);
                    mma16816(acc[2 * np],     a, d0, d1);
                    mma16816(acc[2 * np + 1], a, d2, d3);
                }
            }
        }
    }

    // epilogue: write O fragments
    const int g = lid >> 2, qd = lid & 3;
#pragma unroll
    for (int rh = 0; rh < 2; rh++) {
        const int r = q0 + wr + g + rh * 8;
        float* dst = op + ((size_t)b * L_ + r) * HD_ + h * DK_;
#pragma unroll
        for (int nf = 0; nf < 4; nf++) {
            int col = wc + nf * 8 + qd * 2;
            *(float2*)(dst + col) =
                make_float2(acc[nf][rh * 2], acc[nf][rh * 2 + 1]);
        }
    }
}

// ---------------- launch ---------------------------------------------------
extern "C" void kernel_launch(void* const* d_in, const int* in_sizes, int n_in,
                              void* d_out, int out_size) {
    const float* Q  = (const float*)d_in[0];
    const float* K  = (const float*)d_in[1];
    const float* V  = (const float*)d_in[2];
    const unsigned char* mask = (const unsigned char*)d_in[3];
    const float* Wq = (const float*)d_in[4];
    const float* bq = (const float*)d_in[5];
    const float* Wk = (const float*)d_in[6];
    const float* bk = (const float*)d_in[7];
    const float* Wv = (const float*)d_in[8];
    const float* bv = (const float*)d_in[9];
    const float* Wo = (const float*)d_in[10];
    const float* bo = (const float*)d_in[11];

    float* out  = (float*)d_out;                       // (B, Lq, 512)
    float* attn = out + (size_t)B_ * L_ * DM_;         // (B, H, Lq, Lk)

    float *gq, *gk, *gv, *go, *gpm, *gps, *gl;
    __nv_bfloat16 *gvh, *gvl;
    unsigned char* gm;
    cudaGetSymbolAddress((void**)&gq, g_q);
    cudaGetSymbolAddress((void**)&gk, g_k);
    cudaGetSymbolAddress((void**)&gv, g_v);
    cudaGetSymbolAddress((void**)&go, g_o);
    cudaGetSymbolAddress((void**)&gpm, g_pmax);
    cudaGetSymbolAddress((void**)&gps, g_psum);
    cudaGetSymbolAddress((void**)&gl, g_lse);
    cudaGetSymbolAddress((void**)&gvh, g_vthi);
    cudaGetSymbolAddress((void**)&gvl, g_vtlo);
    cudaGetSymbolAddress((void**)&gm, g_mask);

    cudaFuncSetAttribute(scores_mma_k, cudaFuncAttributeMaxDynamicSharedMemorySize, SC_SMEM);

    mask_convert_k<<<1, 256>>>(mask, gm, B_ * L_);

    const int M = B_ * L_;  // 8192
    sgemm3_k<<<dim3(M / 64, 1, 3), 256>>>(Q, K, V, Wq, Wk, Wv, bq, bk, bv,
                                          gq, gk, gv, M, HD_, DM_);

    vsplit_k<<<dim3(L_ / 128, BH_), 256>>>(gv, gvh, gvl);
    scores_mma_k<<<dim3(L_ / 128, L_ / 128, BH_), 256, SC_SMEM>>>(gq, gk, gm, attn, gpm, gps);
    lse_k<<<(BH_ * L_ + 255) / 256, 256>>>(gpm, gps, gl);
    av_mma_k<<<dim3(L_ / 64, BH_), 256>>>(attn, gvh, gvl, gl, go);

    sgemm3_k<<<dim3(M / 64, DM_ / 128, 1), 256>>>(go, go, go, Wo, Wo, Wo,
                                                  bo, bo, bo, out, out, out,
                                                  M, DM_, HD_);
}

// round 14
// speedup vs baseline: 1.7941x; 1.0806x over previous
#include <cuda_runtime.h>
#include <cuda_bf16.h>
#include <math.h>
#include <stdint.h>

#define B_   4
#define L_   2048
#define DM_  512
#define H_   2
#define DK_  64
#define HD_  128   // H_*DK_
#define BH_  (B_ * H_)

typedef unsigned long long ull;

// ---------------- scratch (device globals; no allocation allowed) ----------
__device__ __align__(16) float g_q[B_ * L_ * HD_];
__device__ __align__(16) float g_k[B_ * L_ * HD_];
__device__ __align__(16) float g_v[B_ * L_ * HD_];
__device__ __align__(16) float g_o[B_ * L_ * HD_];
__device__ __align__(16) float g_pmax[BH_ * L_ * 32];
__device__ __align__(16) float g_psum[BH_ * L_ * 32];
__device__ __align__(16) float g_lse[BH_ * L_];
__device__ __align__(16) __nv_bfloat16 g_vthi[BH_ * DK_ * L_];  // V^T hi: [bh][d][k]
__device__ __align__(16) __nv_bfloat16 g_vtlo[BH_ * DK_ * L_];  // V^T lo
__device__ unsigned char g_mask[B_ * L_];

// ---------------- small helpers --------------------------------------------
__device__ __forceinline__ ull pack2(float x, float y) {
    ull r; asm("mov.b64 %0, {%1,%2};" : "=l"(r) : "f"(x), "f"(y)); return r;
}
__device__ __forceinline__ void unpack2(ull v, float& x, float& y) {
    asm("mov.b64 {%0,%1}, %2;" : "=f"(x), "=f"(y) : "l"(v));
}
__device__ __forceinline__ void ffma2(ull& d, ull a, ull b) {
    asm("fma.rn.f32x2 %0, %1, %2, %3;" : "=l"(d) : "l"(a), "l"(b), "l"(d));
}
__device__ __forceinline__ float tanh_fast(float x) {
    float r; asm("tanh.approx.f32 %0, %1;" : "=f"(r) : "f"(x)); return r;
}
// split (a,b) fp32 -> packed bf16x2 hi (rounded) and lo (residual rounded)
__device__ __forceinline__ void split2(float a, float b, uint32_t& hi, uint32_t& lo) {
    asm("cvt.rn.bf16x2.f32 %0, %1, %2;" : "=r"(hi) : "f"(b), "f"(a));
    float ha = __uint_as_float(hi << 16);
    float hb = __uint_as_float(hi & 0xffff0000u);
    float ra = a - ha, rb = b - hb;
    asm("cvt.rn.bf16x2.f32 %0, %1, %2;" : "=r"(lo) : "f"(rb), "f"(ra));
}
__device__ __forceinline__ uint32_t smem_u32(const void* p) {
    uint32_t a;
    asm("{ .reg .u64 t; cvta.to.shared.u64 t, %1; cvt.u32.u64 %0, t; }"
        : "=r"(a) : "l"(p));
    return a;
}
__device__ __forceinline__ void ldsm4(uint32_t& d0, uint32_t& d1,
                                     uint32_t& d2, uint32_t& d3, uint32_t addr) {
    asm volatile("ldmatrix.sync.aligned.m8n8.x4.shared.b16 {%0,%1,%2,%3}, [%4];"
        : "=r"(d0), "=r"(d1), "=r"(d2), "=r"(d3) : "r"(addr));
}
__device__ __forceinline__ void mma16816(float* c, const uint32_t* a,
                                         uint32_t b0, uint32_t b1) {
    asm volatile(
        "mma.sync.aligned.m16n8k16.row.col.f32.bf16.bf16.f32 "
        "{%0,%1,%2,%3}, {%4,%5,%6,%7}, {%8,%9}, {%0,%1,%2,%3};"
        : "+f"(c[0]), "+f"(c[1]), "+f"(c[2]), "+f"(c[3])
        : "r"(a[0]), "r"(a[1]), "r"(a[2]), "r"(a[3]), "r"(b0), "r"(b1));
}

// ---------------- mask conversion (bool-u8 OR int32 -> u8) -----------------
__global__ void mask_convert_k(const unsigned char* __restrict__ p,
                               unsigned char* __restrict__ out, int n) {
    int tid = threadIdx.x;
    int any = 0;
    for (int i = tid; i < n; i += blockDim.x)
        if ((i & 3) != 0 && p[i] != 0) any = 1;
    any = __syncthreads_or(any);
    if (any) {
        for (int i = tid; i < n; i += blockDim.x) out[i] = p[i] ? 1 : 0;
    } else {
        const int* pi = (const int*)p;
        for (int i = tid; i < n; i += blockDim.x) out[i] = pi[i] ? 1 : 0;
    }
}

// ---------------- SGEMM (3-way by blockIdx.z): C = A @ W + b (fp32/FFMA2) --
__global__ __launch_bounds__(256) void sgemm3_k(
    const float* __restrict__ A0, const float* __restrict__ A1, const float* __restrict__ A2,
    const float* __restrict__ W0, const float* __restrict__ W1, const float* __restrict__ W2,
    const float* __restrict__ b0, const float* __restrict__ b1, const float* __restrict__ b2,
    float* __restrict__ C0, float* __restrict__ C1, float* __restrict__ C2,
    int M, int N, int K)
{
    const float *A, *W, *bias; float* C;
    if (blockIdx.z == 0)      { A = A0; W = W0; bias = b0; C = C0; }
    else if (blockIdx.z == 1) { A = A1; W = W1; bias = b1; C = C1; }
    else                      { A = A2; W = W2; bias = b2; C = C2; }

    __shared__ float As[16][65];
    __shared__ float Bs[16][128];
    const int tid = threadIdx.x;
    const int tx = tid & 15, ty = tid >> 4;
    const float* Ab = A + (size_t)blockIdx.x * 64 * K;
    const float* Wb = W + (size_t)blockIdx.y * 128;

    ull acc[4][4];
#pragma unroll
    for (int i = 0; i < 4; i++)
#pragma unroll
        for (int j = 0; j < 4; j++) acc[i][j] = 0ull;

    for (int k0 = 0; k0 < K; k0 += 16) {
        {
            int row = tid >> 2, c4 = tid & 3;
            float4 v = *(const float4*)(Ab + (size_t)row * K + k0 + c4 * 4);
            As[c4 * 4 + 0][row] = v.x;
            As[c4 * 4 + 1][row] = v.y;
            As[c4 * 4 + 2][row] = v.z;
            As[c4 * 4 + 3][row] = v.w;
        }
#pragma unroll
        for (int l = 0; l < 2; l++) {
            int idx = tid + l * 256;
            int row = idx >> 5, c4 = idx & 31;
            *(float4*)&Bs[row][c4 * 4] =
                *(const float4*)(Wb + (size_t)(k0 + row) * N + c4 * 4);
        }
        __syncthreads();
#pragma unroll
        for (int kk = 0; kk < 16; kk++) {
            ull a2[4];
#pragma unroll
            for (int i = 0; i < 4; i++) {
                float a = As[kk][ty * 4 + i];
                a2[i] = pack2(a, a);
            }
            ulonglong2 bb0 = *(const ulonglong2*)&Bs[kk][tx * 8];
            ulonglong2 bb1 = *(const ulonglong2*)&Bs[kk][tx * 8 + 4];
#pragma unroll
            for (int i = 0; i < 4; i++) {
                ffma2(acc[i][0], a2[i], bb0.x);
                ffma2(acc[i][1], a2[i], bb0.y);
                ffma2(acc[i][2], a2[i], bb1.x);
                ffma2(acc[i][3], a2[i], bb1.y);
            }
        }
        __syncthreads();
    }
    float4 ba = *(const float4*)(bias + blockIdx.y * 128 + tx * 8);
    float4 bbv = *(const float4*)(bias + blockIdx.y * 128 + tx * 8 + 4);
#pragma unroll
    for (int i = 0; i < 4; i++) {
        int row = blockIdx.x * 64 + ty * 4 + i;
        float* Crow = C + (size_t)row * N + blockIdx.y * 128 + tx * 8;
        float4 o0, o1;
        unpack2(acc[i][0], o0.x, o0.y);
        unpack2(acc[i][1], o0.z, o0.w);
        unpack2(acc[i][2], o1.x, o1.y);
        unpack2(acc[i][3], o1.z, o1.w);
        o0.x += ba.x;  o0.y += ba.y;  o0.z += ba.z;  o0.w += ba.w;
        o1.x += bbv.x; o1.y += bbv.y; o1.z += bbv.z; o1.w += bbv.w;
        *(float4*)Crow = o0;
        *(float4*)(Crow + 4) = o1;
    }
}

// ---------------- V transpose + bf16 split:  VT[bh][d][k] ------------------
__global__ __launch_bounds__(256) void vsplit_k(
    const float* __restrict__ vp,
    __nv_bfloat16* __restrict__ vthi, __nv_bfloat16* __restrict__ vtlo)
{
    __shared__ float t[128][68];   // stride 272B = 17*16 (float4-aligned rows)
    const int tid = threadIdx.x;
    const int bh = blockIdx.y, b = bh >> 1, h = bh & 1;
    const int k0 = blockIdx.x * 128;
    const float* Vb = vp + ((size_t)b * L_ + k0) * HD_ + h * DK_;
#pragma unroll
    for (int l = 0; l < 8; l++) {
        int idx = tid + l * 256;
        int row = idx >> 4, c4 = idx & 15;
        float4 v = *(const float4*)(Vb + (size_t)row * HD_ + c4 * 4);
        *(float4*)&t[row][c4 * 4] = v;
    }
    __syncthreads();
#pragma unroll
    for (int l = 0; l < 4; l++) {
        int task = tid + l * 256;          // 0..1023
        int d = task >> 4, kc = task & 15; // 8 k's per task
        float x[8];
#pragma unroll
        for (int i = 0; i < 8; i++) x[i] = t[kc * 8 + i][d];
        uint32_t hi[4], lo[4];
#pragma unroll
        for (int i = 0; i < 4; i++) split2(x[2 * i], x[2 * i + 1], hi[i], lo[i]);
        size_t off = ((size_t)bh * DK_ + d) * L_ + k0 + kc * 8;
        *(uint4*)(vthi + off) = make_uint4(hi[0], hi[1], hi[2], hi[3]);
        *(uint4*)(vtlo + off) = make_uint4(lo[0], lo[1], lo[2], lo[3]);
    }
}

// ---------------- scores via mma.sync bf16 split ---------------------------
// grid (Lq/128, Lk/64, B*H), 256 thr (8 warps, each 16 rows x 64 cols).
// SMEM: mask 64B @0; Qhi/Qlo [128][72] bf16; Khi/Klo [64][72] bf16.
#define SC_QH 128
#define SC_QL (SC_QH + 18432)
#define SC_KH (SC_QH + 2 * 18432)
#define SC_KL (SC_KH + 9216)
#define SC_SMEM (SC_KL + 9216)
__global__ __launch_bounds__(256, 2) void scores_mma_k(
    const float* __restrict__ qp, const float* __restrict__ kp,
    const unsigned char* __restrict__ msk, float* __restrict__ attn,
    float* __restrict__ pmax, float* __restrict__ psum)
{
    extern __shared__ char smem[];
    const uint32_t sbase = smem_u32(smem);
    const int tid = threadIdx.x, w = tid >> 5, lid = tid & 31;
    const int bh = blockIdx.z, b = bh >> 1, h = bh & 1;
    const int q0 = blockIdx.x * 128, k0 = blockIdx.y * 64;
    const int wr = w * 16;

    if (tid < 64) smem[tid] = (char)msk[b * L_ + k0 + tid];

    const float* Qb = qp + ((size_t)b * L_ + q0) * HD_ + h * DK_;
    const float* Kb = kp + ((size_t)b * L_ + k0) * HD_ + h * DK_;
#pragma unroll
    for (int l = 0; l < 8; l++) {          // Q: 128x64 fp32 = 2048 f4
        int idx = tid + l * 256;
        int row = idx >> 4, c4 = idx & 15;
        uint32_t off = (uint32_t)(row * 144 + c4 * 8);
        float4 v = *(const float4*)(Qb + (size_t)row * HD_ + c4 * 4);
        uint32_t h0, l0, h1, l1;
        split2(v.x, v.y, h0, l0); split2(v.z, v.w, h1, l1);
        *(uint2*)(smem + SC_QH + off) = make_uint2(h0, h1);
        *(uint2*)(smem + SC_QL + off) = make_uint2(l0, l1);
    }
#pragma unroll
    for (int l = 0; l < 4; l++) {          // K: 64x64 fp32 = 1024 f4
        int idx = tid + l * 256;
        int row = idx >> 4, c4 = idx & 15;
        uint32_t off = (uint32_t)(row * 144 + c4 * 8);
        float4 u = *(const float4*)(Kb + (size_t)row * HD_ + c4 * 4);
        uint32_t h0, l0, h1, l1;
        split2(u.x, u.y, h0, l0); split2(u.z, u.w, h1, l1);
        *(uint2*)(smem + SC_KH + off) = make_uint2(h0, h1);
        *(uint2*)(smem + SC_KL + off) = make_uint2(l0, l1);
    }
    __syncthreads();

    float acc[8][4];
#pragma unroll
    for (int j = 0; j < 8; j++)
#pragma unroll
        for (int r = 0; r < 4; r++) acc[j][r] = 0.f;

    const uint32_t At[3] = {SC_QH, SC_QH, SC_QL};
    const uint32_t Bt[3] = {SC_KH, SC_KL, SC_KH};
#pragma unroll
    for (int p = 0; p < 3; p++) {
        const uint32_t ab = sbase + At[p], bb = sbase + Bt[p];
#pragma unroll
        for (int kf = 0; kf < 4; kf++) {
            uint32_t a[4];
            uint32_t addr = ab + (uint32_t)((wr + (lid & 15)) * 144
                          + kf * 32 + (lid >> 4) * 16);
            ldsm4(a[0], a[1], a[2], a[3], addr);
#pragma unroll
            for (int np = 0; np < 4; np++) {
                uint32_t d0, d1, d2, d3;
                uint32_t baddr = bb + (uint32_t)((np * 16 + ((lid >> 4) * 8)
                               + (lid & 7)) * 144 + kf * 32 + ((lid >> 3) & 1) * 16);
                ldsm4(d0, d1, d2, d3, baddr);
                mma16816(acc[2 * np],     a, d0, d1);
                mma16816(acc[2 * np + 1], a, d2, d3);
            }
        }
    }
    __syncthreads();   // all ldmatrix done; smem tiles reusable as staging

    float* stage = (float*)(smem + SC_QH);   // [128][68] fp32 (stride 272B)
    const int g = lid >> 2, qd = lid & 3;
#pragma unroll
    for (int rh = 0; rh < 2; rh++) {
        const int r = wr + g + rh * 8;
        float vbuf[16];
        float m = -1e30f;
#pragma unroll
        for (int nf = 0; nf < 8; nf++) {
            int col = nf * 8 + qd * 2;
            float t0 = tanh_fast(acc[nf][rh * 2] * 0.125f) * 10.0f;
            float t1 = tanh_fast(acc[nf][rh * 2 + 1] * 0.125f) * 10.0f;
            if (smem[col])     t0 = -10.0f;
            if (smem[col + 1]) t1 = -10.0f;
            vbuf[nf * 2] = t0; vbuf[nf * 2 + 1] = t1;
            m = fmaxf(m, fmaxf(t0, t1));
            *(float2*)(stage + r * 68 + col) = make_float2(t0, t1);
        }
        float s = 0.f;
#pragma unroll
        for (int e = 0; e < 16; e++) s += __expf(vbuf[e] - m);
#pragma unroll
        for (int off = 1; off <= 2; off <<= 1) {
            float mo = __shfl_xor_sync(0xffffffffu, m, off);
            float so = __shfl_xor_sync(0xffffffffu, s, off);
            float nm = fmaxf(m, mo);
            s = s * __expf(m - nm) + so * __expf(mo - nm);
            m = nm;
        }
        if (qd == 0) {
            size_t pidx = (((size_t)bh * L_ + q0 + r) << 5) + blockIdx.y;
            pmax[pidx] = m;
            psum[pidx] = s;
        }
    }
    __syncthreads();

    // coalesced copy staging -> attn (128x64 = 2048 float4)
    float* dstb = attn + (((size_t)bh * L_ + q0)) * L_ + k0;
#pragma unroll
    for (int l = 0; l < 8; l++) {
        int idx = tid + l * 256;
        int row = idx >> 4, c4 = idx & 15;
        *(float4*)(dstb + (size_t)row * L_ + c4 * 4) =
            *(const float4*)(stage + row * 68 + c4 * 4);
    }
}

// ---------------- lse finalize: merge 32 partials per row ------------------
__global__ __launch_bounds__(256) void lse_k(
    const float* __restrict__ pmax, const float* __restrict__ psum,
    float* __restrict__ lse)
{
    int i = blockIdx.x * 256 + threadIdx.x;
    if (i >= BH_ * L_) return;
    const float* pm = pmax + ((size_t)i << 5);
    const float* ps = psum + ((size_t)i << 5);
    float gm = -1e30f;
#pragma unroll
    for (int t = 0; t < 32; t++) gm = fmaxf(gm, pm[t]);
    float s = 0.f;
#pragma unroll
    for (int t = 0; t < 32; t++) s += ps[t] * __expf(pm[t] - gm);
    lse[i] = gm + logf(s);
}

// ---------------- AV via mma.sync: double-buffered pipeline ----------------
// grid (Lq/64, B*H), 256 thr (8 warps, 4x2 of 16x32 tiles). K chunks of 64.
// Dynamic smem: lse 256B + 2 stages x {Ahi,Alo,Bh,Bl} (4 x 9216B each).
#define AV_STG 36864
#define AV_SMEM (256 + 2 * AV_STG)
__global__ __launch_bounds__(256) void av_mma_k(
    float* __restrict__ attn, const __nv_bfloat16* __restrict__ vthi,
    const __nv_bfloat16* __restrict__ vtlo, const float* __restrict__ lse,
    float* __restrict__ op)
{
    extern __shared__ char smem[];
    const uint32_t sbase = smem_u32(smem);
    const int tid = threadIdx.x, w = tid >> 5, lid = tid & 31;
    const int bh = blockIdx.y, b = bh >> 1, h = bh & 1;
    const int q0 = blockIdx.x * 64;
    const int wr = (w >> 1) * 16, wc = (w & 1) * 32;
    float* lse_s = (float*)smem;          // 64 floats

    if (tid < 64) lse_s[tid] = lse[bh * L_ + q0 + tid];
    __syncthreads();

    float* Ag = attn + ((size_t)bh * L_ + q0) * L_;
    const __nv_bfloat16* Bhg = vthi + (size_t)bh * DK_ * L_;
    const __nv_bfloat16* Blg = vtlo + (size_t)bh * DK_ * L_;

    float acc[4][4];
#pragma unroll
    for (int i = 0; i < 4; i++)
#pragma unroll
        for (int j = 0; j < 4; j++) acc[i][j] = 0.f;

    // stage-internal offsets: Ahi 0, Alo 9216, Bh 18432, Bl 27648
    const uint32_t At[3] = {0, 0, 9216};
    const uint32_t Bt[3] = {18432, 27648, 18432};

    // ---- chunk loader: finalize attn, split, fill stage ----
    auto load_chunk = [&](int c, char* stg) {
        const int k0 = c * 64;
#pragma unroll
        for (int l = 0; l < 4; l++) {      // attn 64x64 fp32 = 1024 f4
            int idx = tid + l * 256;
            int row = idx >> 4, c4 = idx & 15;
            float* p = Ag + (size_t)row * L_ + k0 + c4 * 4;
            float4 v = *(const float4*)p;
            float ls = lse_s[row];
            v.x -= ls; v.y -= ls; v.z -= ls; v.w -= ls;
            *(float4*)p = v;               // finalized attn output
            uint32_t h0, l0, h1, l1;
            split2(v.x, v.y, h0, l0); split2(v.z, v.w, h1, l1);
            uint32_t off = (uint32_t)(row * 144 + c4 * 8);
            *(uint2*)(stg + off) = make_uint2(h0, h1);
            *(uint2*)(stg + 9216 + off) = make_uint2(l0, l1);
        }
#pragma unroll
        for (int l = 0; l < 4; l++) {      // VT hi/lo: 2 x 64x64 bf16
            int idx = tid + l * 256;       // 1024 uint4s total
            int t = idx >> 9, row = (idx >> 3) & 63, ch = idx & 7;
            const __nv_bfloat16* src =
                (t ? Blg : Bhg) + (size_t)row * L_ + k0 + ch * 8;
            uint4 d = *(const uint4*)src;
            *(uint4*)(stg + 18432 + t * 9216 + row * 144 + ch * 16) = d;
        }
    };

    load_chunk(0, smem + 256);
    __syncthreads();

    for (int c = 0; c < 32; c++) {
        const int st = c & 1;
        if (c + 1 < 32) load_chunk(c + 1, smem + 256 + (st ^ 1) * AV_STG);

        const uint32_t cb = sbase + 256 + st * AV_STG;
#pragma unroll
        for (int p = 0; p < 3; p++) {
            const uint32_t ab = cb + At[p], bb = cb + Bt[p];
#pragma unroll
            for (int kf = 0; kf < 4; kf++) {
                uint32_t a[4];
                uint32_t addr = ab + (uint32_t)((wr + (lid & 15)) * 144
                              + kf * 32 + (lid >> 4) * 16);
                ldsm4(a[0], a[1], a[2], a[3], addr);
#pragma unroll
                for (int np = 0; np < 2; np++) {
                    uint32_t d0, d1, d2, d3;
                    uint32_t baddr = bb + (uint32_t)((wc + np * 16
                                   + ((lid >> 4) * 8) + (lid & 7)) * 144
                                   + kf * 32 + ((lid >> 3) & 1) * 16);
                    ldsm4(d0, d1, d2, d3, baddr);
                    mma16816(acc[2 * np],     a, d0, d1);
                    mma16816(acc[2 * np + 1], a, d2, d3);
                }
            }
        }
        __syncthreads();
    }

    // epilogue: write O fragments
    const int g = lid >> 2, qd = lid & 3;
#pragma unroll
    for (int rh = 0; rh < 2; rh++) {
        const int r = q0 + wr + g + rh * 8;
        float* dst = op + ((size_t)b * L_ + r) * HD_ + h * DK_;
#pragma unroll
        for (int nf = 0; nf < 4; nf++) {
            int col = wc + nf * 8 + qd * 2;
            *(float2*)(dst + col) =
                make_float2(acc[nf][rh * 2], acc[nf][rh * 2 + 1]);
        }
    }
}

// ---------------- launch ---------------------------------------------------
extern "C" void kernel_launch(void* const* d_in, const int* in_sizes, int n_in,
                              void* d_out, int out_size) {
    const float* Q  = (const float*)d_in[0];
    const float* K  = (const float*)d_in[1];
    const float* V  = (const float*)d_in[2];
    const unsigned char* mask = (const unsigned char*)d_in[3];
    const float* Wq = (const float*)d_in[4];
    const float* bq = (const float*)d_in[5];
    const float* Wk = (const float*)d_in[6];
    const float* bk = (const float*)d_in[7];
    const float* Wv = (const float*)d_in[8];
    const float* bv = (const float*)d_in[9];
    const float* Wo = (const float*)d_in[10];
    const float* bo = (const float*)d_in[11];

    float* out  = (float*)d_out;                       // (B, Lq, 512)
    float* attn = out + (size_t)B_ * L_ * DM_;         // (B, H, Lq, Lk)

    float *gq, *gk, *gv, *go, *gpm, *gps, *gl;
    __nv_bfloat16 *gvh, *gvl;
    unsigned char* gm;
    cudaGetSymbolAddress((void**)&gq, g_q);
    cudaGetSymbolAddress((void**)&gk, g_k);
    cudaGetSymbolAddress((void**)&gv, g_v);
    cudaGetSymbolAddress((void**)&go, g_o);
    cudaGetSymbolAddress((void**)&gpm, g_pmax);
    cudaGetSymbolAddress((void**)&gps, g_psum);
    cudaGetSymbolAddress((void**)&gl, g_lse);
    cudaGetSymbolAddress((void**)&gvh, g_vthi);
    cudaGetSymbolAddress((void**)&gvl, g_vtlo);
    cudaGetSymbolAddress((void**)&gm, g_mask);

    cudaFuncSetAttribute(scores_mma_k, cudaFuncAttributeMaxDynamicSharedMemorySize, SC_SMEM);
    cudaFuncSetAttribute(av_mma_k, cudaFuncAttributeMaxDynamicSharedMemorySize, AV_SMEM);

    mask_convert_k<<<1, 256>>>(mask, gm, B_ * L_);

    const int M = B_ * L_;  // 8192
    sgemm3_k<<<dim3(M / 64, 1, 3), 256>>>(Q, K, V, Wq, Wk, Wv, bq, bk, bv,
                                          gq, gk, gv, M, HD_, DM_);

    vsplit_k<<<dim3(L_ / 128, BH_), 256>>>(gv, gvh, gvl);
    scores_mma_k<<<dim3(L_ / 128, L_ / 64, BH_), 256, SC_SMEM>>>(gq, gk, gm, attn, gpm, gps);
    lse_k<<<(BH_ * L_ + 255) / 256, 256>>>(gpm, gps, gl);
    av_mma_k<<<dim3(L_ / 64, BH_), 256, AV_SMEM>>>(attn, gvh, gvl, gl, go);

    sgemm3_k<<<dim3(M / 64, DM_ / 128, 1), 256>>>(go, go, go, Wo, Wo, Wo,
                                                  bo, bo, bo, out, out, out,
                                                  M, DM_, HD_);
}

// round 16
// speedup vs baseline: 2.4438x; 1.3621x over previous
#include <cuda_runtime.h>
#include <cuda_bf16.h>
#include <math.h>
#include <stdint.h>

#define B_   4
#define L_   2048
#define DM_  512
#define H_   2
#define DK_  64
#define HD_  128   // H_*DK_
#define BH_  (B_ * H_)

typedef unsigned long long ull;

// ---------------- scratch (device globals; no allocation allowed) ----------
__device__ __align__(16) float g_q[B_ * L_ * HD_];
__device__ __align__(16) float g_k[B_ * L_ * HD_];
__device__ __align__(16) float g_v[B_ * L_ * HD_];
__device__ __align__(16) float g_o[B_ * L_ * HD_];
__device__ __align__(16) float g_pmax[BH_ * L_ * 32];
__device__ __align__(16) float g_psum[BH_ * L_ * 32];
__device__ __align__(16) float g_lse[BH_ * L_];
__device__ __align__(16) __nv_bfloat16 g_vthi[BH_ * DK_ * L_];  // V^T hi: [bh][d][k]
__device__ __align__(16) __nv_bfloat16 g_vtlo[BH_ * DK_ * L_];  // V^T lo
// transposed+split weights: Wq@0, Wk@65536, Wv@131072, Wo@196608 (each [N][K])
__device__ __align__(16) __nv_bfloat16 g_wthi[262144];
__device__ __align__(16) __nv_bfloat16 g_wtlo[262144];
__device__ unsigned char g_mask[B_ * L_];

// ---------------- small helpers --------------------------------------------
__device__ __forceinline__ float tanh_fast(float x) {
    float r; asm("tanh.approx.f32 %0, %1;" : "=f"(r) : "f"(x)); return r;
}
// split (a,b) fp32 -> packed bf16x2 hi (rounded) and lo (residual rounded)
__device__ __forceinline__ void split2(float a, float b, uint32_t& hi, uint32_t& lo) {
    asm("cvt.rn.bf16x2.f32 %0, %1, %2;" : "=r"(hi) : "f"(b), "f"(a));
    float ha = __uint_as_float(hi << 16);
    float hb = __uint_as_float(hi & 0xffff0000u);
    float ra = a - ha, rb = b - hb;
    asm("cvt.rn.bf16x2.f32 %0, %1, %2;" : "=r"(lo) : "f"(rb), "f"(ra));
}
__device__ __forceinline__ uint32_t smem_u32(const void* p) {
    uint32_t a;
    asm("{ .reg .u64 t; cvta.to.shared.u64 t, %1; cvt.u32.u64 %0, t; }"
        : "=r"(a) : "l"(p));
    return a;
}
__device__ __forceinline__ void ldsm4(uint32_t& d0, uint32_t& d1,
                                     uint32_t& d2, uint32_t& d3, uint32_t addr) {
    asm volatile("ldmatrix.sync.aligned.m8n8.x4.shared.b16 {%0,%1,%2,%3}, [%4];"
        : "=r"(d0), "=r"(d1), "=r"(d2), "=r"(d3) : "r"(addr));
}
__device__ __forceinline__ void mma16816(float* c, const uint32_t* a,
                                         uint32_t b0, uint32_t b1) {
    asm volatile(
        "mma.sync.aligned.m16n8k16.row.col.f32.bf16.bf16.f32 "
        "{%0,%1,%2,%3}, {%4,%5,%6,%7}, {%8,%9}, {%0,%1,%2,%3};"
        : "+f"(c[0]), "+f"(c[1]), "+f"(c[2]), "+f"(c[3])
        : "r"(a[0]), "r"(a[1]), "r"(a[2]), "r"(a[3]), "r"(b0), "r"(b1));
}

// ---------------- mask conversion (bool-u8 OR int32 -> u8) -----------------
__global__ void mask_convert_k(const unsigned char* __restrict__ p,
                               unsigned char* __restrict__ out, int n) {
    int tid = threadIdx.x;
    int any = 0;
    for (int i = tid; i < n; i += blockDim.x)
        if ((i & 3) != 0 && p[i] != 0) any = 1;
    any = __syncthreads_or(any);
    if (any) {
        for (int i = tid; i < n; i += blockDim.x) out[i] = p[i] ? 1 : 0;
    } else {
        const int* pi = (const int*)p;
        for (int i = tid; i < n; i += blockDim.x) out[i] = pi[i] ? 1 : 0;
    }
}

// ---------------- weight transpose + bf16 split ----------------------------
// src [K,N] fp32 row-major -> Wt[N][K] bf16 hi/lo at per-matrix offset.
__global__ __launch_bounds__(256) void wsplit_k(
    const float* __restrict__ Wq, const float* __restrict__ Wk,
    const float* __restrict__ Wv, const float* __restrict__ Wo,
    __nv_bfloat16* __restrict__ wthi, __nv_bfloat16* __restrict__ wtlo)
{
    __shared__ float t[128][68];
    const int tid = threadIdx.x;
    const int z = blockIdx.z;
    const int K_ = (z < 3) ? 512 : 128;
    const int N_ = (z < 3) ? 128 : 512;
    const int n0 = blockIdx.x * 64, k0 = blockIdx.y * 128;
    if (n0 >= N_ || k0 >= K_) return;
    const float* src = (z == 0) ? Wq : (z == 1) ? Wk : (z == 2) ? Wv : Wo;
    const size_t moff = (z < 3) ? (size_t)z * 65536 : 196608;

#pragma unroll
    for (int l = 0; l < 8; l++) {          // [128 k][64 n] fp32
        int idx = tid + l * 256;
        int row = idx >> 4, c4 = idx & 15;
        float4 v = *(const float4*)(src + (size_t)(k0 + row) * N_ + n0 + c4 * 4);
        *(float4*)&t[row][c4 * 4] = v;
    }
    __syncthreads();
#pragma unroll
    for (int l = 0; l < 4; l++) {
        int task = tid + l * 256;          // 0..1023
        int kc = task >> 6, n = task & 63; // n fastest -> conflict-free gather
        float x[8];
#pragma unroll
        for (int i = 0; i < 8; i++) x[i] = t[kc * 8 + i][n];
        uint32_t hi[4], lo[4];
#pragma unroll
        for (int i = 0; i < 4; i++) split2(x[2 * i], x[2 * i + 1], hi[i], lo[i]);
        size_t off = moff + (size_t)(n0 + n) * K_ + k0 + kc * 8;
        *(uint4*)(wthi + off) = make_uint4(hi[0], hi[1], hi[2], hi[3]);
        *(uint4*)(wtlo + off) = make_uint4(lo[0], lo[1], lo[2], lo[3]);
    }
}

// ---------------- projection GEMM via mma.sync bf16 split ------------------
// C[M,N] = A[M,K] @ W + bias, W pre-transposed/split as Wt[N][K] bf16.
// grid (M/128, N/64, nz); 256 thr (8 warps x 16 rows x 64 cols); K chunks 64.
#define PJ_AH 0
#define PJ_AL 18432
#define PJ_BH 36864
#define PJ_BL 46080
#define PJ_BIAS 55296
#define PJ_SMEM (PJ_BIAS + 256)
__global__ __launch_bounds__(256, 2) void proj_mma_k(
    const float* __restrict__ A0, const float* __restrict__ A1,
    const float* __restrict__ A2,
    const __nv_bfloat16* __restrict__ wthi, const __nv_bfloat16* __restrict__ wtlo,
    const float* __restrict__ b0, const float* __restrict__ b1,
    const float* __restrict__ b2,
    float* __restrict__ C0, float* __restrict__ C1, float* __restrict__ C2,
    int N, int K, int wbase, int wstride)
{
    extern __shared__ char smem[];
    const uint32_t sbase = smem_u32(smem);
    const int tid = threadIdx.x, w = tid >> 5, lid = tid & 31;
    const int z = blockIdx.z;
    const float* A    = (z == 0) ? A0 : (z == 1) ? A1 : A2;
    const float* bias = (z == 0) ? b0 : (z == 1) ? b1 : b2;
    float* C          = (z == 0) ? C0 : (z == 1) ? C1 : C2;
    const __nv_bfloat16* wh = wthi + wbase + z * wstride;
    const __nv_bfloat16* wl = wtlo + wbase + z * wstride;
    const int m0 = blockIdx.x * 128, n0 = blockIdx.y * 64;
    const int wr = w * 16;
    float* bias_s = (float*)(smem + PJ_BIAS);
    if (tid < 64) bias_s[tid] = bias[n0 + tid];

    float acc[8][4];
#pragma unroll
    for (int j = 0; j < 8; j++)
#pragma unroll
        for (int r = 0; r < 4; r++) acc[j][r] = 0.f;

    const uint32_t At[3] = {PJ_AH, PJ_AH, PJ_AL};
    const uint32_t Bt[3] = {PJ_BH, PJ_BL, PJ_BH};

    for (int kc = 0; kc < K; kc += 64) {
        __syncthreads();
#pragma unroll
        for (int l = 0; l < 8; l++) {      // A tile 128x64 fp32, split
            int idx = tid + l * 256;
            int row = idx >> 4, c4 = idx & 15;
            float4 v = *(const float4*)(A + (size_t)(m0 + row) * K + kc + c4 * 4);
            uint32_t h0, l0, h1, l1;
            split2(v.x, v.y, h0, l0); split2(v.z, v.w, h1, l1);
            uint32_t off = (uint32_t)(row * 144 + c4 * 8);
            *(uint2*)(smem + PJ_AH + off) = make_uint2(h0, h1);
            *(uint2*)(smem + PJ_AL + off) = make_uint2(l0, l1);
        }
#pragma unroll
        for (int l = 0; l < 4; l++) {      // Wt tiles 64n x 64k bf16 hi/lo
            int idx = tid + l * 256;       // 1024 uint4s
            int t = idx >> 9, row = (idx >> 3) & 63, ch = idx & 7;
            const __nv_bfloat16* src =
                (t ? wl : wh) + (size_t)(n0 + row) * K + kc + ch * 8;
            uint4 d = *(const uint4*)src;
            *(uint4*)(smem + PJ_BH + t * 9216 + row * 144 + ch * 16) = d;
        }
        __syncthreads();
#pragma unroll
        for (int p = 0; p < 3; p++) {
            const uint32_t ab = sbase + At[p], bb = sbase + Bt[p];
#pragma unroll
            for (int kf = 0; kf < 4; kf++) {
                uint32_t a[4];
                uint32_t addr = ab + (uint32_t)((wr + (lid & 15)) * 144
                              + kf * 32 + (lid >> 4) * 16);
                ldsm4(a[0], a[1], a[2], a[3], addr);
#pragma unroll
                for (int np = 0; np < 4; np++) {
                    uint32_t d0, d1, d2, d3;
                    uint32_t baddr = bb + (uint32_t)((np * 16 + ((lid >> 4) * 8)
                                   + (lid & 7)) * 144 + kf * 32
                                   + ((lid >> 3) & 1) * 16);
                    ldsm4(d0, d1, d2, d3, baddr);
                    mma16816(acc[2 * np],     a, d0, d1);
                    mma16816(acc[2 * np + 1], a, d2, d3);
                }
            }
        }
    }

    // epilogue: bias + fragment writes
    const int g = lid >> 2, qd = lid & 3;
#pragma unroll
    for (int rh = 0; rh < 2; rh++) {
        const int r = m0 + wr + g + rh * 8;
        float* dst = C + (size_t)r * N + n0;
#pragma unroll
        for (int nf = 0; nf < 8; nf++) {
            int col = nf * 8 + qd * 2;
            *(float2*)(dst + col) = make_float2(
                acc[nf][rh * 2]     + bias_s[col],
                acc[nf][rh * 2 + 1] + bias_s[col + 1]);
        }
    }
}

// ---------------- V transpose + bf16 split:  VT[bh][d][k] ------------------
__global__ __launch_bounds__(256) void vsplit_k(
    const float* __restrict__ vp,
    __nv_bfloat16* __restrict__ vthi, __nv_bfloat16* __restrict__ vtlo)
{
    __shared__ float t[128][68];   // stride 272B = 17*16 (float4-aligned rows)
    const int tid = threadIdx.x;
    const int bh = blockIdx.y, b = bh >> 1, h = bh & 1;
    const int k0 = blockIdx.x * 128;
    const float* Vb = vp + ((size_t)b * L_ + k0) * HD_ + h * DK_;
#pragma unroll
    for (int l = 0; l < 8; l++) {
        int idx = tid + l * 256;
        int row = idx >> 4, c4 = idx & 15;
        float4 v = *(const float4*)(Vb + (size_t)row * HD_ + c4 * 4);
        *(float4*)&t[row][c4 * 4] = v;
    }
    __syncthreads();
#pragma unroll
    for (int l = 0; l < 4; l++) {
        int task = tid + l * 256;          // 0..1023
        int d = task >> 4, kc = task & 15; // 8 k's per task
        float x[8];
#pragma unroll
        for (int i = 0; i < 8; i++) x[i] = t[kc * 8 + i][d];
        uint32_t hi[4], lo[4];
#pragma unroll
        for (int i = 0; i < 4; i++) split2(x[2 * i], x[2 * i + 1], hi[i], lo[i]);
        size_t off = ((size_t)bh * DK_ + d) * L_ + k0 + kc * 8;
        *(uint4*)(vthi + off) = make_uint4(hi[0], hi[1], hi[2], hi[3]);
        *(uint4*)(vtlo + off) = make_uint4(lo[0], lo[1], lo[2], lo[3]);
    }
}

// ---------------- scores via mma.sync bf16 split ---------------------------
// grid (Lq/128, Lk/64, B*H), 256 thr (8 warps, each 16 rows x 64 cols).
#define SC_QH 128
#define SC_QL (SC_QH + 18432)
#define SC_KH (SC_QH + 2 * 18432)
#define SC_KL (SC_KH + 9216)
#define SC_SMEM (SC_KL + 9216)
__global__ __launch_bounds__(256, 2) void scores_mma_k(
    const float* __restrict__ qp, const float* __restrict__ kp,
    const unsigned char* __restrict__ msk, float* __restrict__ attn,
    float* __restrict__ pmax, float* __restrict__ psum)
{
    extern __shared__ char smem[];
    const uint32_t sbase = smem_u32(smem);
    const int tid = threadIdx.x, w = tid >> 5, lid = tid & 31;
    const int bh = blockIdx.z, b = bh >> 1, h = bh & 1;
    const int q0 = blockIdx.x * 128, k0 = blockIdx.y * 64;
    const int wr = w * 16;

    if (tid < 64) smem[tid] = (char)msk[b * L_ + k0 + tid];

    const float* Qb = qp + ((size_t)b * L_ + q0) * HD_ + h * DK_;
    const float* Kb = kp + ((size_t)b * L_ + k0) * HD_ + h * DK_;
#pragma unroll
    for (int l = 0; l < 8; l++) {          // Q: 128x64 fp32 = 2048 f4
        int idx = tid + l * 256;
        int row = idx >> 4, c4 = idx & 15;
        uint32_t off = (uint32_t)(row * 144 + c4 * 8);
        float4 v = *(const float4*)(Qb + (size_t)row * HD_ + c4 * 4);
        uint32_t h0, l0, h1, l1;
        split2(v.x, v.y, h0, l0); split2(v.z, v.w, h1, l1);
        *(uint2*)(smem + SC_QH + off) = make_uint2(h0, h1);
        *(uint2*)(smem + SC_QL + off) = make_uint2(l0, l1);
    }
#pragma unroll
    for (int l = 0; l < 4; l++) {          // K: 64x64 fp32 = 1024 f4
        int idx = tid + l * 256;
        int row = idx >> 4, c4 = idx & 15;
        uint32_t off = (uint32_t)(row * 144 + c4 * 8);
        float4 u = *(const float4*)(Kb + (size_t)row * HD_ + c4 * 4);
        uint32_t h0, l0, h1, l1;
        split2(u.x, u.y, h0, l0); split2(u.z, u.w, h1, l1);
        *(uint2*)(smem + SC_KH + off) = make_uint2(h0, h1);
        *(uint2*)(smem + SC_KL + off) = make_uint2(l0, l1);
    }
    __syncthreads();

    float acc[8][4];
#pragma unroll
    for (int j = 0; j < 8; j++)
#pragma unroll
        for (int r = 0; r < 4; r++) acc[j][r] = 0.f;

    const uint32_t At[3] = {SC_QH, SC_QH, SC_QL};
    const uint32_t Bt[3] = {SC_KH, SC_KL, SC_KH};
#pragma unroll
    for (int p = 0; p < 3; p++) {
        const uint32_t ab = sbase + At[p], bb = sbase + Bt[p];
#pragma unroll
        for (int kf = 0; kf < 4; kf++) {
            uint32_t a[4];
            uint32_t addr = ab + (uint32_t)((wr + (lid & 15)) * 144
                          + kf * 32 + (lid >> 4) * 16);
            ldsm4(a[0], a[1], a[2], a[3], addr);
#pragma unroll
            for (int np = 0; np < 4; np++) {
                uint32_t d0, d1, d2, d3;
                uint32_t baddr = bb + (uint32_t)((np * 16 + ((lid >> 4) * 8)
                               + (lid & 7)) * 144 + kf * 32 + ((lid >> 3) & 1) * 16);
                ldsm4(d0, d1, d2, d3, baddr);
                mma16816(acc[2 * np],     a, d0, d1);
                mma16816(acc[2 * np + 1], a, d2, d3);
            }
        }
    }
    __syncthreads();   // all ldmatrix done; smem tiles reusable as staging

    float* stage = (float*)(smem + SC_QH);   // [128][68] fp32 (stride 272B)
    const int g = lid >> 2, qd = lid & 3;
#pragma unroll
    for (int rh = 0; rh < 2; rh++) {
        const int r = wr + g + rh * 8;
        float vbuf[16];
        float m = -1e30f;
#pragma unroll
        for (int nf = 0; nf < 8; nf++) {
            int col = nf * 8 + qd * 2;
            float t0 = tanh_fast(acc[nf][rh * 2] * 0.125f) * 10.0f;
            float t1 = tanh_fast(acc[nf][rh * 2 + 1] * 0.125f) * 10.0f;
            if (smem[col])     t0 = -10.0f;
            if (smem[col + 1]) t1 = -10.0f;
            vbuf[nf * 2] = t0; vbuf[nf * 2 + 1] = t1;
            m = fmaxf(m, fmaxf(t0, t1));
            *(float2*)(stage + r * 68 + col) = make_float2(t0, t1);
        }
        float s = 0.f;
#pragma unroll
        for (int e = 0; e < 16; e++) s += __expf(vbuf[e] - m);
#pragma unroll
        for (int off = 1; off <= 2; off <<= 1) {
            float mo = __shfl_xor_sync(0xffffffffu, m, off);
            float so = __shfl_xor_sync(0xffffffffu, s, off);
            float nm = fmaxf(m, mo);
            s = s * __expf(m - nm) + so * __expf(mo - nm);
            m = nm;
        }
        if (qd == 0) {
            size_t pidx = (((size_t)bh * L_ + q0 + r) << 5) + blockIdx.y;
            pmax[pidx] = m;
            psum[pidx] = s;
        }
    }
    __syncthreads();

    // coalesced copy staging -> attn (128x64 = 2048 float4)
    float* dstb = attn + (((size_t)bh * L_ + q0)) * L_ + k0;
#pragma unroll
    for (int l = 0; l < 8; l++) {
        int idx = tid + l * 256;
        int row = idx >> 4, c4 = idx & 15;
        *(float4*)(dstb + (size_t)row * L_ + c4 * 4) =
            *(const float4*)(stage + row * 68 + c4 * 4);
    }
}

// ---------------- lse finalize: merge 32 partials per row ------------------
__global__ __launch_bounds__(256) void lse_k(
    const float* __restrict__ pmax, const float* __restrict__ psum,
    float* __restrict__ lse)
{
    int i = blockIdx.x * 256 + threadIdx.x;
    if (i >= BH_ * L_) return;
    const float* pm = pmax + ((size_t)i << 5);
    const float* ps = psum + ((size_t)i << 5);
    float gm = -1e30f;
#pragma unroll
    for (int t = 0; t < 32; t++) gm = fmaxf(gm, pm[t]);
    float s = 0.f;
#pragma unroll
    for (int t = 0; t < 32; t++) s += ps[t] * __expf(pm[t] - gm);
    lse[i] = gm + logf(s);
}

// ---------------- AV via mma.sync: double-buffered pipeline ----------------
#define AV_STG 36864
#define AV_SMEM (256 + 2 * AV_STG)
__global__ __launch_bounds__(256) void av_mma_k(
    float* __restrict__ attn, const __nv_bfloat16* __restrict__ vthi,
    const __nv_bfloat16* __restrict__ vtlo, const float* __restrict__ lse,
    float* __restrict__ op)
{
    extern __shared__ char smem[];
    const uint32_t sbase = smem_u32(smem);
    const int tid = threadIdx.x, w = tid >> 5, lid = tid & 31;
    const int bh = blockIdx.y, b = bh >> 1, h = bh & 1;
    const int q0 = blockIdx.x * 64;
    const int wr = (w >> 1) * 16, wc = (w & 1) * 32;
    float* lse_s = (float*)smem;          // 64 floats

    if (tid < 64) lse_s[tid] = lse[bh * L_ + q0 + tid];
    __syncthreads();

    float* Ag = attn + ((size_t)bh * L_ + q0) * L_;
    const __nv_bfloat16* Bhg = vthi + (size_t)bh * DK_ * L_;
    const __nv_bfloat16* Blg = vtlo + (size_t)bh * DK_ * L_;

    float acc[4][4];
#pragma unroll
    for (int i = 0; i < 4; i++)
#pragma unroll
        for (int j = 0; j < 4; j++) acc[i][j] = 0.f;

    const uint32_t At[3] = {0, 0, 9216};
    const uint32_t Bt[3] = {18432, 27648, 18432};

    auto load_chunk = [&](int c, char* stg) {
        const int k0 = c * 64;
#pragma unroll
        for (int l = 0; l < 4; l++) {      // attn 64x64 fp32 = 1024 f4
            int idx = tid + l * 256;
            int row = idx >> 4, c4 = idx & 15;
            float* p = Ag + (size_t)row * L_ + k0 + c4 * 4;
            float4 v = *(const float4*)p;
            float ls = lse_s[row];
            v.x -= ls; v.y -= ls; v.z -= ls; v.w -= ls;
            *(float4*)p = v;               // finalized attn output
            uint32_t h0, l0, h1, l1;
            split2(v.x, v.y, h0, l0); split2(v.z, v.w, h1, l1);
            uint32_t off = (uint32_t)(row * 144 + c4 * 8);
            *(uint2*)(stg + off) = make_uint2(h0, h1);
            *(uint2*)(stg + 9216 + off) = make_uint2(l0, l1);
        }
#pragma unroll
        for (int l = 0; l < 4; l++) {      // VT hi/lo: 2 x 64x64 bf16
            int idx = tid + l * 256;
            int t = idx >> 9, row = (idx >> 3) & 63, ch = idx & 7;
            const __nv_bfloat16* src =
                (t ? Blg : Bhg) + (size_t)row * L_ + k0 + ch * 8;
            uint4 d = *(const uint4*)src;
            *(uint4*)(stg + 18432 + t * 9216 + row * 144 + ch * 16) = d;
        }
    };

    load_chunk(0, smem + 256);
    __syncthreads();

    for (int c = 0; c < 32; c++) {
        const int st = c & 1;
        if (c + 1 < 32) load_chunk(c + 1, smem + 256 + (st ^ 1) * AV_STG);

        const uint32_t cb = sbase + 256 + st * AV_STG;
#pragma unroll
        for (int p = 0; p < 3; p++) {
            const uint32_t ab = cb + At[p], bb = cb + Bt[p];
#pragma unroll
            for (int kf = 0; kf < 4; kf++) {
                uint32_t a[4];
                uint32_t addr = ab + (uint32_t)((wr + (lid & 15)) * 144
                              + kf * 32 + (lid >> 4) * 16);
                ldsm4(a[0], a[1], a[2], a[3], addr);
#pragma unroll
                for (int np = 0; np < 2; np++) {
                    uint32_t d0, d1, d2, d3;
                    uint32_t baddr = bb + (uint32_t)((wc + np * 16
                                   + ((lid >> 4) * 8) + (lid & 7)) * 144
                                   + kf * 32 + ((lid >> 3) & 1) * 16);
                    ldsm4(d0, d1, d2, d3, baddr);
                    mma16816(acc[2 * np],     a, d0, d1);
                    mma16816(acc[2 * np + 1], a, d2, d3);
                }
            }
        }
        __syncthreads();
    }

    const int g = lid >> 2, qd = lid & 3;
#pragma unroll
    for (int rh = 0; rh < 2; rh++) {
        const int r = q0 + wr + g + rh * 8;
        float* dst = op + ((size_t)b * L_ + r) * HD_ + h * DK_;
#pragma unroll
        for (int nf = 0; nf < 4; nf++) {
            int col = wc + nf * 8 + qd * 2;
            *(float2*)(dst + col) =
                make_float2(acc[nf][rh * 2], acc[nf][rh * 2 + 1]);
        }
    }
}

// ---------------- launch ---------------------------------------------------
extern "C" void kernel_launch(void* const* d_in, const int* in_sizes, int n_in,
                              void* d_out, int out_size) {
    const float* Q  = (const float*)d_in[0];
    const float* K  = (const float*)d_in[1];
    const float* V  = (const float*)d_in[2];
    const unsigned char* mask = (const unsigned char*)d_in[3];
    const float* Wq = (const float*)d_in[4];
    const float* bq = (const float*)d_in[5];
    const float* Wk = (const float*)d_in[6];
    const float* bk = (const float*)d_in[7];
    const float* Wv = (const float*)d_in[8];
    const float* bv = (const float*)d_in[9];
    const float* Wo = (const float*)d_in[10];
    const float* bo = (const float*)d_in[11];

    float* out  = (float*)d_out;                       // (B, Lq, 512)
    float* attn = out + (size_t)B_ * L_ * DM_;         // (B, H, Lq, Lk)

    float *gq, *gk, *gv, *go, *gpm, *gps, *gl;
    __nv_bfloat16 *gvh, *gvl, *gwh, *gwl;
    unsigned char* gm;
    cudaGetSymbolAddress((void**)&gq, g_q);
    cudaGetSymbolAddress((void**)&gk, g_k);
    cudaGetSymbolAddress((void**)&gv, g_v);
    cudaGetSymbolAddress((void**)&go, g_o);
    cudaGetSymbolAddress((void**)&gpm, g_pmax);
    cudaGetSymbolAddress((void**)&gps, g_psum);
    cudaGetSymbolAddress((void**)&gl, g_lse);
    cudaGetSymbolAddress((void**)&gvh, g_vthi);
    cudaGetSymbolAddress((void**)&gvl, g_vtlo);
    cudaGetSymbolAddress((void**)&gwh, g_wthi);
    cudaGetSymbolAddress((void**)&gwl, g_wtlo);
    cudaGetSymbolAddress((void**)&gm, g_mask);

    cudaFuncSetAttribute(scores_mma_k, cudaFuncAttributeMaxDynamicSharedMemorySize, SC_SMEM);
    cudaFuncSetAttribute(av_mma_k, cudaFuncAttributeMaxDynamicSharedMemorySize, AV_SMEM);
    cudaFuncSetAttribute(proj_mma_k, cudaFuncAttributeMaxDynamicSharedMemorySize, PJ_SMEM);

    mask_convert_k<<<1, 256>>>(mask, gm, B_ * L_);
    wsplit_k<<<dim3(8, 4, 4), 256>>>(Wq, Wk, Wv, Wo, gwh, gwl);

    const int M = B_ * L_;  // 8192
    // QKV projections on tensor pipe (Wt offsets 0/65536/131072)
    proj_mma_k<<<dim3(M / 128, HD_ / 64, 3), 256, PJ_SMEM>>>(
        Q, K, V, gwh, gwl, bq, bk, bv, gq, gk, gv, HD_, DM_, 0, 65536);

    vsplit_k<<<dim3(L_ / 128, BH_), 256>>>(gv, gvh, gvl);
    scores_mma_k<<<dim3(L_ / 128, L_ / 64, BH_), 256, SC_SMEM>>>(gq, gk, gm, attn, gpm, gps);
    lse_k<<<(BH_ * L_ + 255) / 256, 256>>>(gpm, gps, gl);
    av_mma_k<<<dim3(L_ / 64, BH_), 256, AV_SMEM>>>(attn, gvh, gvl, gl, go);

    // output projection (Wt offset 196608)
    proj_mma_k<<<dim3(M / 128, DM_ / 64, 1), 256, PJ_SMEM>>>(
        go, go, go, gwh, gwl, bo, bo, bo, out, out, out, DM_, HD_, 196608, 0);
}